// round 1
// baseline (speedup 1.0000x reference)
#include <cuda_runtime.h>
#include <math.h>

#define CEMB 1024
#define NHEADS 16
#define HS 64
#define DFF 4096
#define BB 4
#define TT 2048
#define MROWS (BB*TT)   // 8192

// ---- scratch (static device arrays; no allocation in kernel_launch) ----
__device__ float g_h  [(size_t)MROWS * CEMB];      // 32 MB  (ln out, reused)
__device__ float g_qkv[(size_t)MROWS * 3 * CEMB];  // 96 MB
__device__ float g_y  [(size_t)MROWS * CEMB];      // 32 MB  (attention out)
__device__ float g_x2 [(size_t)MROWS * CEMB];      // 32 MB  (after proj residual)
__device__ float g_ff [(size_t)MROWS * DFF];       // 128 MB (MLP hidden)

// ======================= LayerNorm =======================
// one block (256 threads) per row of 1024; each thread owns exactly one float4
__global__ __launch_bounds__(256) void ln_kernel(const float* __restrict__ x,
                                                 const float* __restrict__ g,
                                                 const float* __restrict__ b,
                                                 float* __restrict__ out)
{
    int row = blockIdx.x;
    int t = threadIdx.x;
    float4 v = ((const float4*)(x + (size_t)row * CEMB))[t];
    float s  = v.x + v.y + v.z + v.w;
    float ss = v.x*v.x + v.y*v.y + v.z*v.z + v.w*v.w;
    #pragma unroll
    for (int o = 16; o > 0; o >>= 1) {
        s  += __shfl_xor_sync(0xffffffffu, s,  o);
        ss += __shfl_xor_sync(0xffffffffu, ss, o);
    }
    __shared__ float red[16];
    int warp = t >> 5, lane = t & 31;
    if (lane == 0) { red[warp] = s; red[warp + 8] = ss; }
    __syncthreads();
    float sum = 0.f, sumsq = 0.f;
    #pragma unroll
    for (int w = 0; w < 8; w++) { sum += red[w]; sumsq += red[w + 8]; }
    float mu   = sum * (1.0f / CEMB);
    float var  = sumsq * (1.0f / CEMB) - mu * mu;
    float rstd = rsqrtf(var + 1e-5f);
    float4 gv = ((const float4*)g)[t];
    float4 bv = ((const float4*)b)[t];
    float4 o;
    o.x = (v.x - mu) * rstd * gv.x + bv.x;
    o.y = (v.y - mu) * rstd * gv.y + bv.y;
    o.z = (v.z - mu) * rstd * gv.z + bv.z;
    o.w = (v.w - mu) * rstd * gv.w + bv.w;
    ((float4*)(out + (size_t)row * CEMB))[t] = o;
}

// ======================= SGEMM =======================
__device__ __forceinline__ float gelu_f(float x) {
    float t = tanhf(0.79788456080286536f * (x + 0.044715f * x * x * x));
    return 0.5f * x * (1.0f + t);
}

// C[M,N] = A[M,K] @ B[K,N] + bias, EPI: 0=bias, 1=bias+residual, 2=bias+gelu
// 128x128 tile, BK=8, 256 threads, 8x8 per thread.
template<int EPI>
__global__ __launch_bounds__(256) void sgemm_kernel(
    const float* __restrict__ A, const float* __restrict__ Bm,
    const float* __restrict__ bias, const float* __restrict__ R,
    float* __restrict__ C, int M, int N, int K)
{
    __shared__ __align__(16) float As[8][128];   // transposed: As[k][m]
    __shared__ __align__(16) float Bs[8][128];   // Bs[k][n]
    int tid = threadIdx.x;
    int tx = tid & 15, ty = tid >> 4;
    int m0 = blockIdx.y * 128, n0 = blockIdx.x * 128;

    float acc[8][8];
    #pragma unroll
    for (int i = 0; i < 8; i++)
        #pragma unroll
        for (int j = 0; j < 8; j++) acc[i][j] = 0.f;

    int arow = tid >> 1;           // 0..127
    int acol = (tid & 1) * 4;      // 0 or 4
    int brow = tid >> 5;           // 0..7
    int bcol = (tid & 31) * 4;     // 0..124
    const float* Ap = A  + (size_t)(m0 + arow) * K + acol;
    const float* Bp = Bm + (size_t)brow * N + n0 + bcol;

    for (int k0 = 0; k0 < K; k0 += 8) {
        float4 av = *(const float4*)(Ap + k0);
        float4 bv = *(const float4*)(Bp + (size_t)k0 * N);
        __syncthreads();
        As[acol + 0][arow] = av.x;
        As[acol + 1][arow] = av.y;
        As[acol + 2][arow] = av.z;
        As[acol + 3][arow] = av.w;
        *(float4*)(&Bs[brow][bcol]) = bv;
        __syncthreads();
        #pragma unroll
        for (int kk = 0; kk < 8; kk++) {
            float a[8], bb[8];
            *(float4*)(&a[0])  = *(const float4*)(&As[kk][ty * 8]);
            *(float4*)(&a[4])  = *(const float4*)(&As[kk][ty * 8 + 4]);
            *(float4*)(&bb[0]) = *(const float4*)(&Bs[kk][tx * 8]);
            *(float4*)(&bb[4]) = *(const float4*)(&Bs[kk][tx * 8 + 4]);
            #pragma unroll
            for (int i = 0; i < 8; i++)
                #pragma unroll
                for (int j = 0; j < 8; j++)
                    acc[i][j] += a[i] * bb[j];
        }
    }

    int col = n0 + tx * 8;
    float4 bias0 = *(const float4*)(bias + col);
    float4 bias1 = *(const float4*)(bias + col + 4);
    #pragma unroll
    for (int i = 0; i < 8; i++) {
        int row = m0 + ty * 8 + i;
        float o[8];
        #pragma unroll
        for (int j = 0; j < 8; j++) o[j] = acc[i][j];
        o[0] += bias0.x; o[1] += bias0.y; o[2] += bias0.z; o[3] += bias0.w;
        o[4] += bias1.x; o[5] += bias1.y; o[6] += bias1.z; o[7] += bias1.w;
        if (EPI == 1) {
            const float* rr = R + (size_t)row * N + col;
            float4 r0 = *(const float4*)rr;
            float4 r1 = *(const float4*)(rr + 4);
            o[0] += r0.x; o[1] += r0.y; o[2] += r0.z; o[3] += r0.w;
            o[4] += r1.x; o[5] += r1.y; o[6] += r1.z; o[7] += r1.w;
        }
        if (EPI == 2) {
            #pragma unroll
            for (int j = 0; j < 8; j++) o[j] = gelu_f(o[j]);
        }
        float* cc = C + (size_t)row * N + col;
        *(float4*)cc       = make_float4(o[0], o[1], o[2], o[3]);
        *(float4*)(cc + 4) = make_float4(o[4], o[5], o[6], o[7]);
    }
}

// ======================= Flash attention (fp32) =======================
// grid: (T/64 q-blocks, B*H); block 256 threads (16x16), each thread a 4x4 tile.
// Q,K stored d-major (transposed) in smem so the S inner loop is 2 conflict-free
// LDS.128 per k-step; P (written transposed) aliases the K buffer -> 48 KB static.
__global__ __launch_bounds__(256) void attn_kernel(const float* __restrict__ qkv,
                                                   float* __restrict__ y)
{
    __shared__ __align__(16) float Qt[64 * 64];  // Qt[d][m]
    __shared__ __align__(16) float Kt[64 * 64];  // Kt[d][n]; later Pt[n][m]
    __shared__ __align__(16) float Vs[64 * 64];  // Vs[n][d]

    int qblk = blockIdx.x;
    int bh = blockIdx.y;
    int b = bh >> 4, h = bh & 15;
    int q0 = qblk * 64;
    const int RS = 3 * CEMB;
    const float* qbase = qkv + (size_t)b * TT * RS + h * HS;
    const float* kbase = qbase + CEMB;
    const float* vbase = qbase + 2 * CEMB;

    int tid = threadIdx.x;
    int tx = tid & 15, ty = tid >> 4;

    // load Q tile, transposed into Qt[d][m]
    #pragma unroll
    for (int i = tid; i < 1024; i += 256) {
        int r = i >> 4;
        int dq = (i & 15) * 4;
        float4 v = *(const float4*)(qbase + (size_t)(q0 + r) * RS + dq);
        Qt[(dq + 0) * 64 + r] = v.x;
        Qt[(dq + 1) * 64 + r] = v.y;
        Qt[(dq + 2) * 64 + r] = v.z;
        Qt[(dq + 3) * 64 + r] = v.w;
    }

    float m_i[4], l_i[4], acc[4][4];
    #pragma unroll
    for (int i = 0; i < 4; i++) {
        m_i[i] = -INFINITY; l_i[i] = 0.f;
        #pragma unroll
        for (int j = 0; j < 4; j++) acc[i][j] = 0.f;
    }

    for (int jb = 0; jb <= qblk; jb++) {
        int j0 = jb * 64;
        __syncthreads();   // previous PV reads (Kt/Vs) done before overwrite
        #pragma unroll
        for (int i = tid; i < 1024; i += 256) {
            int r = i >> 4;
            int dq = (i & 15) * 4;
            float4 kv = *(const float4*)(kbase + (size_t)(j0 + r) * RS + dq);
            Kt[(dq + 0) * 64 + r] = kv.x;
            Kt[(dq + 1) * 64 + r] = kv.y;
            Kt[(dq + 2) * 64 + r] = kv.z;
            Kt[(dq + 3) * 64 + r] = kv.w;
            float4 vv = *(const float4*)(vbase + (size_t)(j0 + r) * RS + dq);
            *(float4*)(&Vs[r * 64 + dq]) = vv;
        }
        __syncthreads();

        // S = Q K^T (4x4 per thread)
        float s[4][4];
        #pragma unroll
        for (int i = 0; i < 4; i++)
            #pragma unroll
            for (int j = 0; j < 4; j++) s[i][j] = 0.f;
        #pragma unroll 8
        for (int kk = 0; kk < 64; kk++) {
            float4 a4 = *(const float4*)(&Qt[kk * 64 + ty * 4]);
            float4 b4 = *(const float4*)(&Kt[kk * 64 + tx * 4]);
            float a[4]  = {a4.x, a4.y, a4.z, a4.w};
            float bb[4] = {b4.x, b4.y, b4.z, b4.w};
            #pragma unroll
            for (int i = 0; i < 4; i++)
                #pragma unroll
                for (int j = 0; j < 4; j++)
                    s[i][j] += a[i] * bb[j];
        }

        bool diag = (jb == qblk);
        #pragma unroll
        for (int i = 0; i < 4; i++)
            #pragma unroll
            for (int j = 0; j < 4; j++) {
                s[i][j] *= 0.125f;   // hs^-0.5
                if (diag && (tx * 4 + j) > (ty * 4 + i)) s[i][j] = -INFINITY;
            }

        // online softmax stats (row groups = 16 contiguous lanes)
        float rmax[4];
        #pragma unroll
        for (int i = 0; i < 4; i++)
            rmax[i] = fmaxf(fmaxf(s[i][0], s[i][1]), fmaxf(s[i][2], s[i][3]));
        #pragma unroll
        for (int o = 8; o > 0; o >>= 1)
            #pragma unroll
            for (int i = 0; i < 4; i++)
                rmax[i] = fmaxf(rmax[i], __shfl_xor_sync(0xffffffffu, rmax[i], o));

        float alpha[4], rsum[4];
        #pragma unroll
        for (int i = 0; i < 4; i++) {
            float mn = fmaxf(m_i[i], rmax[i]);
            alpha[i] = __expf(m_i[i] - mn);
            m_i[i] = mn;
            rsum[i] = 0.f;
        }
        #pragma unroll
        for (int i = 0; i < 4; i++)
            #pragma unroll
            for (int j = 0; j < 4; j++) {
                float p = __expf(s[i][j] - m_i[i]);
                s[i][j] = p;
                rsum[i] += p;
            }
        #pragma unroll
        for (int o = 8; o > 0; o >>= 1)
            #pragma unroll
            for (int i = 0; i < 4; i++)
                rsum[i] += __shfl_xor_sync(0xffffffffu, rsum[i], o);
        #pragma unroll
        for (int i = 0; i < 4; i++) {
            l_i[i] = l_i[i] * alpha[i] + rsum[i];
            #pragma unroll
            for (int j = 0; j < 4; j++) acc[i][j] *= alpha[i];
        }

        __syncthreads();   // all Kt reads done before overwriting with P
        #pragma unroll
        for (int i = 0; i < 4; i++)
            #pragma unroll
            for (int j = 0; j < 4; j++)
                Kt[(tx * 4 + j) * 64 + (ty * 4 + i)] = s[i][j];   // Pt[n][m]
        __syncthreads();

        // O += P @ V
        #pragma unroll 8
        for (int n = 0; n < 64; n++) {
            float4 p4 = *(const float4*)(&Kt[n * 64 + ty * 4]);
            float4 v4 = *(const float4*)(&Vs[n * 64 + tx * 4]);
            float p[4]  = {p4.x, p4.y, p4.z, p4.w};
            float vv[4] = {v4.x, v4.y, v4.z, v4.w};
            #pragma unroll
            for (int i = 0; i < 4; i++)
                #pragma unroll
                for (int j = 0; j < 4; j++)
                    acc[i][j] += p[i] * vv[j];
        }
    }

    #pragma unroll
    for (int i = 0; i < 4; i++) {
        float inv = 1.0f / l_i[i];
        size_t row = (size_t)b * TT + q0 + ty * 4 + i;
        *(float4*)(y + row * CEMB + h * HS + tx * 4) =
            make_float4(acc[i][0] * inv, acc[i][1] * inv, acc[i][2] * inv, acc[i][3] * inv);
    }
}

// ======================= launch =======================
extern "C" void kernel_launch(void* const* d_in, const int* in_sizes, int n_in,
                              void* d_out, int out_size)
{
    const float* x      = (const float*)d_in[0];
    const float* ln1_g  = (const float*)d_in[1];
    const float* ln1_b  = (const float*)d_in[2];
    const float* w_attn = (const float*)d_in[3];
    const float* b_attn = (const float*)d_in[4];
    const float* w_proj = (const float*)d_in[5];
    const float* b_proj = (const float*)d_in[6];
    const float* ln2_g  = (const float*)d_in[7];
    const float* ln2_b  = (const float*)d_in[8];
    const float* w_fc   = (const float*)d_in[9];
    const float* b_fc   = (const float*)d_in[10];
    const float* w_fc2  = (const float*)d_in[11];
    const float* b_fc2  = (const float*)d_in[12];
    float* out = (float*)d_out;

    float *h, *qkv, *y, *x2, *ff;
    cudaGetSymbolAddress((void**)&h,   g_h);
    cudaGetSymbolAddress((void**)&qkv, g_qkv);
    cudaGetSymbolAddress((void**)&y,   g_y);
    cudaGetSymbolAddress((void**)&x2,  g_x2);
    cudaGetSymbolAddress((void**)&ff,  g_ff);

    dim3 blk(256);

    // x -> ln1 -> h
    ln_kernel<<<MROWS, blk>>>(x, ln1_g, ln1_b, h);
    // qkv = h @ w_attn + b_attn
    sgemm_kernel<0><<<dim3(3 * CEMB / 128, MROWS / 128), blk>>>(
        h, w_attn, b_attn, nullptr, qkv, MROWS, 3 * CEMB, CEMB);
    // y = causal attention(qkv)
    attn_kernel<<<dim3(TT / 64, BB * NHEADS), blk>>>(qkv, y);
    // x2 = y @ w_proj + b_proj + x
    sgemm_kernel<1><<<dim3(CEMB / 128, MROWS / 128), blk>>>(
        y, w_proj, b_proj, x, x2, MROWS, CEMB, CEMB);
    // h = ln2(x2)
    ln_kernel<<<MROWS, blk>>>(x2, ln2_g, ln2_b, h);
    // ff = gelu(h @ w_fc + b_fc)
    sgemm_kernel<2><<<dim3(DFF / 128, MROWS / 128), blk>>>(
        h, w_fc, b_fc, nullptr, ff, MROWS, DFF, CEMB);
    // out = ff @ w_fc2 + b_fc2 + x2
    sgemm_kernel<1><<<dim3(CEMB / 128, MROWS / 128), blk>>>(
        ff, w_fc2, b_fc2, x2, out, MROWS, CEMB, DFF);
}

// round 3
// speedup vs baseline: 1.9067x; 1.9067x over previous
#include <cuda_runtime.h>
#include <cuda_bf16.h>
#include <math.h>
#include <stdint.h>

#define CEMB 1024
#define NHEADS 16
#define HS 64
#define DFF 4096
#define BB 4
#define TT 2048
#define MROWS (BB*TT)   // 8192

// GEMM tile config
#define BM 128
#define BN 128
#define BKE 64          // k elems per stage (128 bytes of bf16)
#define GT 256          // threads per GEMM CTA

// ---------------- scratch (static device arrays) ----------------
__device__ float g_qkv[(size_t)MROWS * 3 * CEMB];          // fp32 qkv
__device__ float g_x2 [(size_t)MROWS * CEMB];              // fp32 after proj residual
__device__ __nv_bfloat16 g_hh[(size_t)MROWS * CEMB];       // ln out hi
__device__ __nv_bfloat16 g_hl[(size_t)MROWS * CEMB];       // ln out lo
__device__ __nv_bfloat16 g_yh[(size_t)MROWS * CEMB];       // attn out hi
__device__ __nv_bfloat16 g_yl[(size_t)MROWS * CEMB];       // attn out lo
__device__ __nv_bfloat16 g_fh[(size_t)MROWS * DFF];        // mlp hidden hi
__device__ __nv_bfloat16 g_fl[(size_t)MROWS * DFF];        // mlp hidden lo
// weights, transposed to [N,K] K-major, split hi/lo
__device__ __nv_bfloat16 g_wah[(size_t)3*CEMB * CEMB];
__device__ __nv_bfloat16 g_wal[(size_t)3*CEMB * CEMB];
__device__ __nv_bfloat16 g_wph[(size_t)CEMB * CEMB];
__device__ __nv_bfloat16 g_wpl[(size_t)CEMB * CEMB];
__device__ __nv_bfloat16 g_wfh[(size_t)DFF * CEMB];
__device__ __nv_bfloat16 g_wfl[(size_t)DFF * CEMB];
__device__ __nv_bfloat16 g_w2h[(size_t)CEMB * DFF];
__device__ __nv_bfloat16 g_w2l[(size_t)CEMB * DFF];

// ---------------- PTX helpers (arch-portable: ldmatrix/mma/cp.async) ----------------
__device__ __forceinline__ uint32_t smem_u32(const void* p) {
    uint32_t a;
    asm("{ .reg .u64 t; cvta.to.shared.u64 t, %1; cvt.u32.u64 %0, t; }" : "=r"(a) : "l"(p));
    return a;
}
#define CP_ASYNC16(s, g) \
    asm volatile("cp.async.cg.shared.global [%0], [%1], 16;" :: "r"(s), "l"(g) : "memory")
#define CP_COMMIT() asm volatile("cp.async.commit_group;" ::: "memory")
#define CP_WAIT1()  asm volatile("cp.async.wait_group 1;" ::: "memory")
#define CP_WAIT0()  asm volatile("cp.async.wait_group 0;" ::: "memory")
#define LDSM_X4(r0, r1, r2, r3, addr) \
    asm volatile("ldmatrix.sync.aligned.m8n8.x4.shared.b16 {%0,%1,%2,%3}, [%4];" \
        : "=r"(r0), "=r"(r1), "=r"(r2), "=r"(r3) : "r"(addr))
#define MMA16816(c, a, b0v, b1v) \
    asm volatile("mma.sync.aligned.m16n8k16.row.col.f32.bf16.bf16.f32 " \
        "{%0,%1,%2,%3}, {%4,%5,%6,%7}, {%8,%9}, {%0,%1,%2,%3};" \
        : "+f"((c)[0]), "+f"((c)[1]), "+f"((c)[2]), "+f"((c)[3]) \
        : "r"((a)[0]), "r"((a)[1]), "r"((a)[2]), "r"((a)[3]), "r"(b0v), "r"(b1v))

__device__ __forceinline__ uint32_t sw128(uint32_t off) { return off ^ ((off >> 3) & 0x70); }

__device__ __forceinline__ float gelu_f(float x) {
    float t = tanhf(0.79788456080286536f * (x + 0.044715f * x * x * x));
    return 0.5f * x * (1.0f + t);
}

union P4 { __nv_bfloat16 b[4]; uint2 u; };
__device__ __forceinline__ void split4(const float* v, P4& ph, P4& pl) {
    #pragma unroll
    for (int j = 0; j < 4; j++) {
        __nv_bfloat16 hb = __float2bfloat16(v[j]);
        ph.b[j] = hb;
        pl.b[j] = __float2bfloat16(v[j] - __bfloat162float(hb));
    }
}
union P2 { __nv_bfloat16 b[2]; uint32_t u; };

// ---------------- weight transpose + split: W[K,N] fp32 -> Wh/Wl [N,K] bf16 ----------------
__global__ __launch_bounds__(256) void wsplit_kernel(const float* __restrict__ W,
    __nv_bfloat16* __restrict__ Wh, __nv_bfloat16* __restrict__ Wl, int K, int N)
{
    __shared__ float t[32][33];
    int n0 = blockIdx.x * 32, k0 = blockIdx.y * 32;
    int tx = threadIdx.x & 31, ty = threadIdx.x >> 5;
    #pragma unroll
    for (int r = ty; r < 32; r += 8)
        t[r][tx] = W[(size_t)(k0 + r) * N + n0 + tx];
    __syncthreads();
    #pragma unroll
    for (int r = ty; r < 32; r += 8) {
        float v = t[tx][r];   // = W[k0+tx][n0+r]
        __nv_bfloat16 hb = __float2bfloat16(v);
        size_t o = (size_t)(n0 + r) * K + k0 + tx;
        Wh[o] = hb;
        Wl[o] = __float2bfloat16(v - __bfloat162float(hb));
    }
}

// ---------------- LayerNorm -> split bf16 ----------------
__global__ __launch_bounds__(256) void ln_kernel(const float* __restrict__ x,
                                                 const float* __restrict__ g,
                                                 const float* __restrict__ b,
                                                 __nv_bfloat16* __restrict__ oh,
                                                 __nv_bfloat16* __restrict__ ol)
{
    int row = blockIdx.x;
    int t = threadIdx.x;
    float4 v = ((const float4*)(x + (size_t)row * CEMB))[t];
    float s  = v.x + v.y + v.z + v.w;
    float ss = v.x*v.x + v.y*v.y + v.z*v.z + v.w*v.w;
    #pragma unroll
    for (int o = 16; o > 0; o >>= 1) {
        s  += __shfl_xor_sync(0xffffffffu, s,  o);
        ss += __shfl_xor_sync(0xffffffffu, ss, o);
    }
    __shared__ float red[16];
    int warp = t >> 5, lane = t & 31;
    if (lane == 0) { red[warp] = s; red[warp + 8] = ss; }
    __syncthreads();
    float sum = 0.f, sumsq = 0.f;
    #pragma unroll
    for (int w = 0; w < 8; w++) { sum += red[w]; sumsq += red[w + 8]; }
    float mu   = sum * (1.0f / CEMB);
    float var  = sumsq * (1.0f / CEMB) - mu * mu;
    float rstd = rsqrtf(var + 1e-5f);
    float4 gv = ((const float4*)g)[t];
    float4 bv = ((const float4*)b)[t];
    float o[4];
    o[0] = (v.x - mu) * rstd * gv.x + bv.x;
    o[1] = (v.y - mu) * rstd * gv.y + bv.y;
    o[2] = (v.z - mu) * rstd * gv.z + bv.z;
    o[3] = (v.w - mu) * rstd * gv.w + bv.w;
    P4 ph, pl;
    split4(o, ph, pl);
    *(uint2*)(oh + (size_t)row * CEMB + t * 4) = ph.u;
    *(uint2*)(ol + (size_t)row * CEMB + t * 4) = pl.u;
}

// ---------------- HMMA split-bf16 GEMM ----------------
// C[M,N] = (Ah+Al)[M,K] @ (Bh+Bl)[N,K]^T + bias
// EPI: 0 = fp32 out, 1 = fp32 out + residual, 2 = gelu -> bf16 hi/lo out
// 128x128 tile, BK=64 elems, double-buffered cp.async, 8 warps (4m x 2n), warp tile 32x64.
#define STAGE_BYTES 65536   // Ah 16K | Al 16K | Bh 16K | Bl 16K
#define SMEM_GEMM (2 * STAGE_BYTES + 1024)

template<int EPI>
__global__ __launch_bounds__(GT, 1) void gemm_bf16x3(
    const __nv_bfloat16* __restrict__ Ah, const __nv_bfloat16* __restrict__ Al,
    const __nv_bfloat16* __restrict__ Bh, const __nv_bfloat16* __restrict__ Bl,
    const float* __restrict__ bias, const float* __restrict__ R,
    float* __restrict__ Cf, __nv_bfloat16* __restrict__ Ch, __nv_bfloat16* __restrict__ Cl,
    int M, int N, int K)
{
    extern __shared__ char dsm[];
    uintptr_t pa = ((uintptr_t)dsm + 1023) & ~(uintptr_t)1023;
    uint32_t sb = smem_u32((char*)pa);

    int tid = threadIdx.x;
    int wid = tid >> 5, lid = tid & 31;
    int wm = wid >> 1, wn = wid & 1;
    int m0 = blockIdx.y * BM, n0 = blockIdx.x * BN;

    const int NC = K / BKE;

    // per-thread load slots: 4 chunks per tile (A / B, hi & lo)
    int lrow = tid >> 3;          // 0..31  (+32*t)
    int lch  = tid & 7;           // chunk 0..7

    // stage loader
    auto load_stage = [&](int c) {
        int buf = c & 1;
        uint32_t st = sb + buf * STAGE_BYTES;
        int k0 = c * BKE;
        #pragma unroll
        for (int t = 0; t < 4; t++) {
            int row = lrow + t * 32;
            uint32_t so = sw128((uint32_t)(row * 128 + lch * 16));
            size_t ga = (size_t)(m0 + row) * K + k0 + lch * 8;
            CP_ASYNC16(st + so,         (const char*)(Ah + ga));
            CP_ASYNC16(st + 16384 + so, (const char*)(Al + ga));
            size_t gb = (size_t)(n0 + row) * K + k0 + lch * 8;
            CP_ASYNC16(st + 32768 + so, (const char*)(Bh + gb));
            CP_ASYNC16(st + 49152 + so, (const char*)(Bl + gb));
        }
    };

    float acc[2][8][4];
    #pragma unroll
    for (int mi = 0; mi < 2; mi++)
        #pragma unroll
        for (int j = 0; j < 8; j++)
            #pragma unroll
            for (int q = 0; q < 4; q++) acc[mi][j][q] = 0.f;

    // ldmatrix lane geometry
    int lrow16 = lid & 15;        // row within 16-row tile
    int khalf  = lid >> 4;        // 0: k-low 8, 1: k-high 8

    load_stage(0);
    CP_COMMIT();

    for (int c = 0; c < NC; c++) {
        if (c + 1 < NC) { load_stage(c + 1); CP_COMMIT(); CP_WAIT1(); }
        else            { CP_WAIT0(); }
        __syncthreads();

        uint32_t st = sb + (c & 1) * STAGE_BYTES;

        #pragma unroll
        for (int s = 0; s < 4; s++) {
            uint32_t aH[2][4], aL[2][4], bH[4][4], bL[4][4];
            #pragma unroll
            for (int mi = 0; mi < 2; mi++) {
                int row = wm * 32 + mi * 16 + lrow16;
                int ch = (s * 2 + khalf) ^ (row & 7);
                uint32_t ad = st + (uint32_t)(row * 128 + ch * 16);
                LDSM_X4(aH[mi][0], aH[mi][1], aH[mi][2], aH[mi][3], ad);
                LDSM_X4(aL[mi][0], aL[mi][1], aL[mi][2], aL[mi][3], ad + 16384);
            }
            #pragma unroll
            for (int nb = 0; nb < 4; nb++) {
                int row = wn * 64 + nb * 16 + lrow16;
                int ch = (s * 2 + khalf) ^ (row & 7);
                uint32_t bd = st + 32768 + (uint32_t)(row * 128 + ch * 16);
                LDSM_X4(bH[nb][0], bH[nb][1], bH[nb][2], bH[nb][3], bd);
                LDSM_X4(bL[nb][0], bL[nb][1], bL[nb][2], bL[nb][3], bd + 16384);
            }
            #pragma unroll
            for (int mi = 0; mi < 2; mi++) {
                #pragma unroll
                for (int nb = 0; nb < 4; nb++) {
                    MMA16816(acc[mi][nb*2],   aH[mi], bH[nb][0], bH[nb][2]);
                    MMA16816(acc[mi][nb*2],   aH[mi], bL[nb][0], bL[nb][2]);
                    MMA16816(acc[mi][nb*2],   aL[mi], bH[nb][0], bH[nb][2]);
                    MMA16816(acc[mi][nb*2+1], aH[mi], bH[nb][1], bH[nb][3]);
                    MMA16816(acc[mi][nb*2+1], aH[mi], bL[nb][1], bL[nb][3]);
                    MMA16816(acc[mi][nb*2+1], aL[mi], bH[nb][1], bH[nb][3]);
                }
            }
        }
        __syncthreads();
    }

    // ---------------- epilogue ----------------
    int gid = lid >> 2, tig = lid & 3;
    #pragma unroll
    for (int mi = 0; mi < 2; mi++) {
        #pragma unroll
        for (int j = 0; j < 8; j++) {
            int r0 = m0 + wm * 32 + mi * 16 + gid;
            int r1 = r0 + 8;
            int col = n0 + wn * 64 + j * 8 + tig * 2;
            float b0 = bias[col], b1 = bias[col + 1];
            float v0 = acc[mi][j][0] + b0, v1 = acc[mi][j][1] + b1;
            float v2 = acc[mi][j][2] + b0, v3 = acc[mi][j][3] + b1;
            if (EPI == 1) {
                float2 q0 = *(const float2*)(R + (size_t)r0 * N + col);
                float2 q1 = *(const float2*)(R + (size_t)r1 * N + col);
                v0 += q0.x; v1 += q0.y; v2 += q1.x; v3 += q1.y;
            }
            if (EPI == 2) {
                v0 = gelu_f(v0); v1 = gelu_f(v1); v2 = gelu_f(v2); v3 = gelu_f(v3);
                P2 h0, l0, h1, l1;
                h0.b[0] = __float2bfloat16(v0);
                l0.b[0] = __float2bfloat16(v0 - __bfloat162float(h0.b[0]));
                h0.b[1] = __float2bfloat16(v1);
                l0.b[1] = __float2bfloat16(v1 - __bfloat162float(h0.b[1]));
                h1.b[0] = __float2bfloat16(v2);
                l1.b[0] = __float2bfloat16(v2 - __bfloat162float(h1.b[0]));
                h1.b[1] = __float2bfloat16(v3);
                l1.b[1] = __float2bfloat16(v3 - __bfloat162float(h1.b[1]));
                *(uint32_t*)(Ch + (size_t)r0 * N + col) = h0.u;
                *(uint32_t*)(Cl + (size_t)r0 * N + col) = l0.u;
                *(uint32_t*)(Ch + (size_t)r1 * N + col) = h1.u;
                *(uint32_t*)(Cl + (size_t)r1 * N + col) = l1.u;
            } else {
                *(float2*)(Cf + (size_t)r0 * N + col) = make_float2(v0, v1);
                *(float2*)(Cf + (size_t)r1 * N + col) = make_float2(v2, v3);
            }
        }
    }
}

// ---------------- Flash attention (fp32), writes split bf16 ----------------
__global__ __launch_bounds__(256) void attn_kernel(const float* __restrict__ qkv,
                                                   __nv_bfloat16* __restrict__ yh,
                                                   __nv_bfloat16* __restrict__ yl)
{
    __shared__ __align__(16) float Qt[64 * 64];  // Qt[d][m]
    __shared__ __align__(16) float Kt[64 * 64];  // Kt[d][n]; later Pt[n][m]
    __shared__ __align__(16) float Vs[64 * 64];  // Vs[n][d]

    int qblk = blockIdx.x;
    int bh = blockIdx.y;
    int b = bh >> 4, hd = bh & 15;
    int q0 = qblk * 64;
    const int RS = 3 * CEMB;
    const float* qbase = qkv + (size_t)b * TT * RS + hd * HS;
    const float* kbase = qbase + CEMB;
    const float* vbase = qbase + 2 * CEMB;

    int tid = threadIdx.x;
    int tx = tid & 15, ty = tid >> 4;

    #pragma unroll
    for (int i = tid; i < 1024; i += 256) {
        int r = i >> 4;
        int dq = (i & 15) * 4;
        float4 v = *(const float4*)(qbase + (size_t)(q0 + r) * RS + dq);
        Qt[(dq + 0) * 64 + r] = v.x;
        Qt[(dq + 1) * 64 + r] = v.y;
        Qt[(dq + 2) * 64 + r] = v.z;
        Qt[(dq + 3) * 64 + r] = v.w;
    }

    float m_i[4], l_i[4], acc[4][4];
    #pragma unroll
    for (int i = 0; i < 4; i++) {
        m_i[i] = -INFINITY; l_i[i] = 0.f;
        #pragma unroll
        for (int j = 0; j < 4; j++) acc[i][j] = 0.f;
    }

    for (int jb = 0; jb <= qblk; jb++) {
        int j0 = jb * 64;
        __syncthreads();
        #pragma unroll
        for (int i = tid; i < 1024; i += 256) {
            int r = i >> 4;
            int dq = (i & 15) * 4;
            float4 kv = *(const float4*)(kbase + (size_t)(j0 + r) * RS + dq);
            Kt[(dq + 0) * 64 + r] = kv.x;
            Kt[(dq + 1) * 64 + r] = kv.y;
            Kt[(dq + 2) * 64 + r] = kv.z;
            Kt[(dq + 3) * 64 + r] = kv.w;
            float4 vv = *(const float4*)(vbase + (size_t)(j0 + r) * RS + dq);
            *(float4*)(&Vs[r * 64 + dq]) = vv;
        }
        __syncthreads();

        float s[4][4];
        #pragma unroll
        for (int i = 0; i < 4; i++)
            #pragma unroll
            for (int j = 0; j < 4; j++) s[i][j] = 0.f;
        #pragma unroll 8
        for (int kk = 0; kk < 64; kk++) {
            float4 a4 = *(const float4*)(&Qt[kk * 64 + ty * 4]);
            float4 b4 = *(const float4*)(&Kt[kk * 64 + tx * 4]);
            float a[4]  = {a4.x, a4.y, a4.z, a4.w};
            float bb[4] = {b4.x, b4.y, b4.z, b4.w};
            #pragma unroll
            for (int i = 0; i < 4; i++)
                #pragma unroll
                for (int j = 0; j < 4; j++)
                    s[i][j] += a[i] * bb[j];
        }

        bool diag = (jb == qblk);
        #pragma unroll
        for (int i = 0; i < 4; i++)
            #pragma unroll
            for (int j = 0; j < 4; j++) {
                s[i][j] *= 0.125f;
                if (diag && (tx * 4 + j) > (ty * 4 + i)) s[i][j] = -INFINITY;
            }

        float rmax[4];
        #pragma unroll
        for (int i = 0; i < 4; i++)
            rmax[i] = fmaxf(fmaxf(s[i][0], s[i][1]), fmaxf(s[i][2], s[i][3]));
        #pragma unroll
        for (int o = 8; o > 0; o >>= 1)
            #pragma unroll
            for (int i = 0; i < 4; i++)
                rmax[i] = fmaxf(rmax[i], __shfl_xor_sync(0xffffffffu, rmax[i], o));

        float alpha[4], rsum[4];
        #pragma unroll
        for (int i = 0; i < 4; i++) {
            float mn = fmaxf(m_i[i], rmax[i]);
            alpha[i] = __expf(m_i[i] - mn);
            m_i[i] = mn;
            rsum[i] = 0.f;
        }
        #pragma unroll
        for (int i = 0; i < 4; i++)
            #pragma unroll
            for (int j = 0; j < 4; j++) {
                float p = __expf(s[i][j] - m_i[i]);
                s[i][j] = p;
                rsum[i] += p;
            }
        #pragma unroll
        for (int o = 8; o > 0; o >>= 1)
            #pragma unroll
            for (int i = 0; i < 4; i++)
                rsum[i] += __shfl_xor_sync(0xffffffffu, rsum[i], o);
        #pragma unroll
        for (int i = 0; i < 4; i++) {
            l_i[i] = l_i[i] * alpha[i] + rsum[i];
            #pragma unroll
            for (int j = 0; j < 4; j++) acc[i][j] *= alpha[i];
        }

        __syncthreads();
        #pragma unroll
        for (int i = 0; i < 4; i++)
            #pragma unroll
            for (int j = 0; j < 4; j++)
                Kt[(tx * 4 + j) * 64 + (ty * 4 + i)] = s[i][j];
        __syncthreads();

        #pragma unroll 8
        for (int n = 0; n < 64; n++) {
            float4 p4 = *(const float4*)(&Kt[n * 64 + ty * 4]);
            float4 v4 = *(const float4*)(&Vs[n * 64 + tx * 4]);
            float p[4]  = {p4.x, p4.y, p4.z, p4.w};
            float vv[4] = {v4.x, v4.y, v4.z, v4.w};
            #pragma unroll
            for (int i = 0; i < 4; i++)
                #pragma unroll
                for (int j = 0; j < 4; j++)
                    acc[i][j] += p[i] * vv[j];
        }
    }

    #pragma unroll
    for (int i = 0; i < 4; i++) {
        float inv = 1.0f / l_i[i];
        size_t row = (size_t)b * TT + q0 + ty * 4 + i;
        float o[4] = {acc[i][0]*inv, acc[i][1]*inv, acc[i][2]*inv, acc[i][3]*inv};
        P4 ph, pl;
        split4(o, ph, pl);
        size_t ofs = row * CEMB + hd * HS + tx * 4;
        *(uint2*)(yh + ofs) = ph.u;
        *(uint2*)(yl + ofs) = pl.u;
    }
}

// ---------------- launch ----------------
extern "C" void kernel_launch(void* const* d_in, const int* in_sizes, int n_in,
                              void* d_out, int out_size)
{
    const float* x      = (const float*)d_in[0];
    const float* ln1_g  = (const float*)d_in[1];
    const float* ln1_b  = (const float*)d_in[2];
    const float* w_attn = (const float*)d_in[3];
    const float* b_attn = (const float*)d_in[4];
    const float* w_proj = (const float*)d_in[5];
    const float* b_proj = (const float*)d_in[6];
    const float* ln2_g  = (const float*)d_in[7];
    const float* ln2_b  = (const float*)d_in[8];
    const float* w_fc   = (const float*)d_in[9];
    const float* b_fc   = (const float*)d_in[10];
    const float* w_fc2  = (const float*)d_in[11];
    const float* b_fc2  = (const float*)d_in[12];
    float* out = (float*)d_out;

    float *qkv, *x2;
    __nv_bfloat16 *hh, *hl, *yh, *yl, *fh, *fl;
    __nv_bfloat16 *wah, *wal, *wph, *wpl, *wfh, *wfl, *w2h, *w2l;
    cudaGetSymbolAddress((void**)&qkv, g_qkv);
    cudaGetSymbolAddress((void**)&x2,  g_x2);
    cudaGetSymbolAddress((void**)&hh,  g_hh);
    cudaGetSymbolAddress((void**)&hl,  g_hl);
    cudaGetSymbolAddress((void**)&yh,  g_yh);
    cudaGetSymbolAddress((void**)&yl,  g_yl);
    cudaGetSymbolAddress((void**)&fh,  g_fh);
    cudaGetSymbolAddress((void**)&fl,  g_fl);
    cudaGetSymbolAddress((void**)&wah, g_wah);
    cudaGetSymbolAddress((void**)&wal, g_wal);
    cudaGetSymbolAddress((void**)&wph, g_wph);
    cudaGetSymbolAddress((void**)&wpl, g_wpl);
    cudaGetSymbolAddress((void**)&wfh, g_wfh);
    cudaGetSymbolAddress((void**)&wfl, g_wfl);
    cudaGetSymbolAddress((void**)&w2h, g_w2h);
    cudaGetSymbolAddress((void**)&w2l, g_w2l);

    cudaFuncSetAttribute(gemm_bf16x3<0>, cudaFuncAttributeMaxDynamicSharedMemorySize, SMEM_GEMM);
    cudaFuncSetAttribute(gemm_bf16x3<1>, cudaFuncAttributeMaxDynamicSharedMemorySize, SMEM_GEMM);
    cudaFuncSetAttribute(gemm_bf16x3<2>, cudaFuncAttributeMaxDynamicSharedMemorySize, SMEM_GEMM);

    dim3 blk(256);

    // weight transpose + split
    wsplit_kernel<<<dim3(3*CEMB/32, CEMB/32), blk>>>(w_attn, wah, wal, CEMB, 3*CEMB);
    wsplit_kernel<<<dim3(CEMB/32,   CEMB/32), blk>>>(w_proj, wph, wpl, CEMB, CEMB);
    wsplit_kernel<<<dim3(DFF/32,    CEMB/32), blk>>>(w_fc,   wfh, wfl, CEMB, DFF);
    wsplit_kernel<<<dim3(CEMB/32,   DFF/32),  blk>>>(w_fc2,  w2h, w2l, DFF,  CEMB);

    // ln1
    ln_kernel<<<MROWS, blk>>>(x, ln1_g, ln1_b, hh, hl);
    // qkv = h @ w_attn + b_attn  (fp32 out)
    gemm_bf16x3<0><<<dim3(3*CEMB/BN, MROWS/BM), GT, SMEM_GEMM>>>(
        hh, hl, wah, wal, b_attn, nullptr, qkv, nullptr, nullptr, MROWS, 3*CEMB, CEMB);
    // attention
    attn_kernel<<<dim3(TT/64, BB*NHEADS), blk>>>(qkv, yh, yl);
    // x2 = y @ w_proj + b_proj + x
    gemm_bf16x3<1><<<dim3(CEMB/BN, MROWS/BM), GT, SMEM_GEMM>>>(
        yh, yl, wph, wpl, b_proj, x, x2, nullptr, nullptr, MROWS, CEMB, CEMB);
    // ln2
    ln_kernel<<<MROWS, blk>>>(x2, ln2_g, ln2_b, hh, hl);
    // ff = gelu(h @ w_fc + b_fc)  -> bf16 hi/lo
    gemm_bf16x3<2><<<dim3(DFF/BN, MROWS/BM), GT, SMEM_GEMM>>>(
        hh, hl, wfh, wfl, b_fc, nullptr, nullptr, fh, fl, MROWS, DFF, CEMB);
    // out = ff @ w_fc2 + b_fc2 + x2
    gemm_bf16x3<1><<<dim3(CEMB/BN, MROWS/BM), GT, SMEM_GEMM>>>(
        fh, fl, w2h, w2l, b_fc2, x2, out, nullptr, nullptr, MROWS, CEMB, DFF);
}

// round 4
// speedup vs baseline: 2.7729x; 1.4543x over previous
#include <cuda_runtime.h>
#include <cuda_bf16.h>
#include <math.h>
#include <stdint.h>

#define CEMB 1024
#define NHEADS 16
#define HS 64
#define DFF 4096
#define BB 4
#define TT 2048
#define MROWS (BB*TT)   // 8192

#define BM 128
#define BN 128
#define BKE 64
#define GT 256

// ---------------- scratch ----------------
__device__ float g_qkv[(size_t)MROWS * 3 * CEMB];
__device__ float g_x2 [(size_t)MROWS * CEMB];
__device__ __nv_bfloat16 g_hh[(size_t)MROWS * CEMB];
__device__ __nv_bfloat16 g_hl[(size_t)MROWS * CEMB];
__device__ __nv_bfloat16 g_yh[(size_t)MROWS * CEMB];
__device__ __nv_bfloat16 g_yl[(size_t)MROWS * CEMB];
__device__ __nv_bfloat16 g_fh[(size_t)MROWS * DFF];
__device__ __nv_bfloat16 g_fl[(size_t)MROWS * DFF];
__device__ __nv_bfloat16 g_wah[(size_t)3*CEMB * CEMB];
__device__ __nv_bfloat16 g_wal[(size_t)3*CEMB * CEMB];
__device__ __nv_bfloat16 g_wph[(size_t)CEMB * CEMB];
__device__ __nv_bfloat16 g_wpl[(size_t)CEMB * CEMB];
__device__ __nv_bfloat16 g_wfh[(size_t)DFF * CEMB];
__device__ __nv_bfloat16 g_wfl[(size_t)DFF * CEMB];
__device__ __nv_bfloat16 g_w2h[(size_t)CEMB * DFF];
__device__ __nv_bfloat16 g_w2l[(size_t)CEMB * DFF];
__device__ __nv_bfloat16 g_aqh[(size_t)64 * TT * HS];
__device__ __nv_bfloat16 g_aql[(size_t)64 * TT * HS];
__device__ __nv_bfloat16 g_akh[(size_t)64 * TT * HS];
__device__ __nv_bfloat16 g_akl[(size_t)64 * TT * HS];
__device__ __nv_bfloat16 g_avh[(size_t)64 * HS * TT];
__device__ __nv_bfloat16 g_avl[(size_t)64 * HS * TT];

// ---------------- PTX helpers ----------------
__device__ __forceinline__ uint32_t smem_u32(const void* p) {
    uint32_t a;
    asm("{ .reg .u64 t; cvta.to.shared.u64 t, %1; cvt.u32.u64 %0, t; }" : "=r"(a) : "l"(p));
    return a;
}
#define CP_ASYNC16(s, g) \
    asm volatile("cp.async.cg.shared.global [%0], [%1], 16;" :: "r"(s), "l"(g) : "memory")
#define CP_COMMIT() asm volatile("cp.async.commit_group;" ::: "memory")
#define CP_WAIT1()  asm volatile("cp.async.wait_group 1;" ::: "memory")
#define CP_WAIT0()  asm volatile("cp.async.wait_group 0;" ::: "memory")
#define LDSM_X4(r0, r1, r2, r3, addr) \
    asm volatile("ldmatrix.sync.aligned.m8n8.x4.shared.b16 {%0,%1,%2,%3}, [%4];" \
        : "=r"(r0), "=r"(r1), "=r"(r2), "=r"(r3) : "r"(addr))
#define MMA16816(c, a, b0v, b1v) \
    asm volatile("mma.sync.aligned.m16n8k16.row.col.f32.bf16.bf16.f32 " \
        "{%0,%1,%2,%3}, {%4,%5,%6,%7}, {%8,%9}, {%0,%1,%2,%3};" \
        : "+f"((c)[0]), "+f"((c)[1]), "+f"((c)[2]), "+f"((c)[3]) \
        : "r"((a)[0]), "r"((a)[1]), "r"((a)[2]), "r"((a)[3]), "r"(b0v), "r"(b1v))
#define STS32(addr, v) \
    asm volatile("st.shared.b32 [%0], %1;" :: "r"(addr), "r"(v) : "memory")

__device__ __forceinline__ uint32_t sw128(uint32_t off) { return off ^ ((off >> 3) & 0x70); }

__device__ __forceinline__ float gelu_f(float x) {
    float t = tanhf(0.79788456080286536f * (x + 0.044715f * x * x * x));
    return 0.5f * x * (1.0f + t);
}

union P4 { __nv_bfloat16 b[4]; uint2 u; };
__device__ __forceinline__ void split4(const float* v, P4& ph, P4& pl) {
    #pragma unroll
    for (int j = 0; j < 4; j++) {
        __nv_bfloat16 hb = __float2bfloat16(v[j]);
        ph.b[j] = hb;
        pl.b[j] = __float2bfloat16(v[j] - __bfloat162float(hb));
    }
}
union P2 { __nv_bfloat16 b[2]; uint32_t u; };
__device__ __forceinline__ void split2(float v0, float v1, P2& h, P2& l) {
    h.b[0] = __float2bfloat16(v0);
    l.b[0] = __float2bfloat16(v0 - __bfloat162float(h.b[0]));
    h.b[1] = __float2bfloat16(v1);
    l.b[1] = __float2bfloat16(v1 - __bfloat162float(h.b[1]));
}

// ---------------- weight transpose + split ----------------
__global__ __launch_bounds__(256) void wsplit_kernel(const float* __restrict__ W,
    __nv_bfloat16* __restrict__ Wh, __nv_bfloat16* __restrict__ Wl, int K, int N)
{
    __shared__ float t[32][33];
    int n0 = blockIdx.x * 32, k0 = blockIdx.y * 32;
    int tx = threadIdx.x & 31, ty = threadIdx.x >> 5;
    #pragma unroll
    for (int r = ty; r < 32; r += 8)
        t[r][tx] = W[(size_t)(k0 + r) * N + n0 + tx];
    __syncthreads();
    #pragma unroll
    for (int r = ty; r < 32; r += 8) {
        float v = t[tx][r];
        __nv_bfloat16 hb = __float2bfloat16(v);
        size_t o = (size_t)(n0 + r) * K + k0 + tx;
        Wh[o] = hb;
        Wl[o] = __float2bfloat16(v - __bfloat162float(hb));
    }
}

// ---------------- LayerNorm -> split bf16 ----------------
__global__ __launch_bounds__(256) void ln_kernel(const float* __restrict__ x,
                                                 const float* __restrict__ g,
                                                 const float* __restrict__ b,
                                                 __nv_bfloat16* __restrict__ oh,
                                                 __nv_bfloat16* __restrict__ ol)
{
    int row = blockIdx.x;
    int t = threadIdx.x;
    float4 v = ((const float4*)(x + (size_t)row * CEMB))[t];
    float s  = v.x + v.y + v.z + v.w;
    float ss = v.x*v.x + v.y*v.y + v.z*v.z + v.w*v.w;
    #pragma unroll
    for (int o = 16; o > 0; o >>= 1) {
        s  += __shfl_xor_sync(0xffffffffu, s,  o);
        ss += __shfl_xor_sync(0xffffffffu, ss, o);
    }
    __shared__ float red[16];
    int warp = t >> 5, lane = t & 31;
    if (lane == 0) { red[warp] = s; red[warp + 8] = ss; }
    __syncthreads();
    float sum = 0.f, sumsq = 0.f;
    #pragma unroll
    for (int w = 0; w < 8; w++) { sum += red[w]; sumsq += red[w + 8]; }
    float mu   = sum * (1.0f / CEMB);
    float var  = sumsq * (1.0f / CEMB) - mu * mu;
    float rstd = rsqrtf(var + 1e-5f);
    float4 gv = ((const float4*)g)[t];
    float4 bv = ((const float4*)b)[t];
    float o[4];
    o[0] = (v.x - mu) * rstd * gv.x + bv.x;
    o[1] = (v.y - mu) * rstd * gv.y + bv.y;
    o[2] = (v.z - mu) * rstd * gv.z + bv.z;
    o[3] = (v.w - mu) * rstd * gv.w + bv.w;
    P4 ph, pl;
    split4(o, ph, pl);
    *(uint2*)(oh + (size_t)row * CEMB + t * 4) = ph.u;
    *(uint2*)(ol + (size_t)row * CEMB + t * 4) = pl.u;
}

// ---------------- HMMA split-bf16 GEMM ----------------
#define STAGE_BYTES 65536
#define SMEM_GEMM (2 * STAGE_BYTES + 1024)

template<int EPI>
__global__ __launch_bounds__(GT, 1) void gemm_bf16x3(
    const __nv_bfloat16* __restrict__ Ah, const __nv_bfloat16* __restrict__ Al,
    const __nv_bfloat16* __restrict__ Bh, const __nv_bfloat16* __restrict__ Bl,
    const float* __restrict__ bias, const float* __restrict__ R,
    float* __restrict__ Cf, __nv_bfloat16* __restrict__ Ch, __nv_bfloat16* __restrict__ Cl,
    int M, int N, int K)
{
    extern __shared__ char dsm[];
    uintptr_t pa = ((uintptr_t)dsm + 1023) & ~(uintptr_t)1023;
    uint32_t sb = smem_u32((char*)pa);

    int tid = threadIdx.x;
    int wid = tid >> 5, lid = tid & 31;
    int wm = wid >> 1, wn = wid & 1;
    int m0 = blockIdx.y * BM, n0 = blockIdx.x * BN;

    const int NC = K / BKE;
    int lrow = tid >> 3;
    int lch  = tid & 7;

    auto load_stage = [&](int c) {
        int buf = c & 1;
        uint32_t st = sb + buf * STAGE_BYTES;
        int k0 = c * BKE;
        #pragma unroll
        for (int t = 0; t < 4; t++) {
            int row = lrow + t * 32;
            uint32_t so = sw128((uint32_t)(row * 128 + lch * 16));
            size_t ga = (size_t)(m0 + row) * K + k0 + lch * 8;
            CP_ASYNC16(st + so,         (const char*)(Ah + ga));
            CP_ASYNC16(st + 16384 + so, (const char*)(Al + ga));
            size_t gb = (size_t)(n0 + row) * K + k0 + lch * 8;
            CP_ASYNC16(st + 32768 + so, (const char*)(Bh + gb));
            CP_ASYNC16(st + 49152 + so, (const char*)(Bl + gb));
        }
    };

    float acc[2][8][4];
    #pragma unroll
    for (int mi = 0; mi < 2; mi++)
        #pragma unroll
        for (int j = 0; j < 8; j++)
            #pragma unroll
            for (int q = 0; q < 4; q++) acc[mi][j][q] = 0.f;

    int lrow16 = lid & 15;
    int khalf  = lid >> 4;

    load_stage(0);
    CP_COMMIT();

    for (int c = 0; c < NC; c++) {
        if (c + 1 < NC) { load_stage(c + 1); CP_COMMIT(); CP_WAIT1(); }
        else            { CP_WAIT0(); }
        __syncthreads();

        uint32_t st = sb + (c & 1) * STAGE_BYTES;

        #pragma unroll
        for (int s = 0; s < 4; s++) {
            uint32_t aH[2][4], aL[2][4], bH[4][4], bL[4][4];
            #pragma unroll
            for (int mi = 0; mi < 2; mi++) {
                int row = wm * 32 + mi * 16 + lrow16;
                int ch = (s * 2 + khalf) ^ (row & 7);
                uint32_t ad = st + (uint32_t)(row * 128 + ch * 16);
                LDSM_X4(aH[mi][0], aH[mi][1], aH[mi][2], aH[mi][3], ad);
                LDSM_X4(aL[mi][0], aL[mi][1], aL[mi][2], aL[mi][3], ad + 16384);
            }
            #pragma unroll
            for (int nb = 0; nb < 4; nb++) {
                int row = wn * 64 + nb * 16 + lrow16;
                int ch = (s * 2 + khalf) ^ (row & 7);
                uint32_t bd = st + 32768 + (uint32_t)(row * 128 + ch * 16);
                LDSM_X4(bH[nb][0], bH[nb][1], bH[nb][2], bH[nb][3], bd);
                LDSM_X4(bL[nb][0], bL[nb][1], bL[nb][2], bL[nb][3], bd + 16384);
            }
            #pragma unroll
            for (int mi = 0; mi < 2; mi++) {
                #pragma unroll
                for (int nb = 0; nb < 4; nb++) {
                    MMA16816(acc[mi][nb*2],   aH[mi], bH[nb][0], bH[nb][2]);
                    MMA16816(acc[mi][nb*2],   aH[mi], bL[nb][0], bL[nb][2]);
                    MMA16816(acc[mi][nb*2],   aL[mi], bH[nb][0], bH[nb][2]);
                    MMA16816(acc[mi][nb*2+1], aH[mi], bH[nb][1], bH[nb][3]);
                    MMA16816(acc[mi][nb*2+1], aH[mi], bL[nb][1], bL[nb][3]);
                    MMA16816(acc[mi][nb*2+1], aL[mi], bH[nb][1], bH[nb][3]);
                }
            }
        }
        __syncthreads();
    }

    int gid = lid >> 2, tig = lid & 3;
    #pragma unroll
    for (int mi = 0; mi < 2; mi++) {
        #pragma unroll
        for (int j = 0; j < 8; j++) {
            int r0 = m0 + wm * 32 + mi * 16 + gid;
            int r1 = r0 + 8;
            int col = n0 + wn * 64 + j * 8 + tig * 2;
            float b0 = bias[col], b1 = bias[col + 1];
            float v0 = acc[mi][j][0] + b0, v1 = acc[mi][j][1] + b1;
            float v2 = acc[mi][j][2] + b0, v3 = acc[mi][j][3] + b1;
            if (EPI == 1) {
                float2 q0 = *(const float2*)(R + (size_t)r0 * N + col);
                float2 q1 = *(const float2*)(R + (size_t)r1 * N + col);
                v0 += q0.x; v1 += q0.y; v2 += q1.x; v3 += q1.y;
            }
            if (EPI == 2) {
                v0 = gelu_f(v0); v1 = gelu_f(v1); v2 = gelu_f(v2); v3 = gelu_f(v3);
                P2 h0, l0, h1, l1;
                split2(v0, v1, h0, l0);
                split2(v2, v3, h1, l1);
                *(uint32_t*)(Ch + (size_t)r0 * N + col) = h0.u;
                *(uint32_t*)(Cl + (size_t)r0 * N + col) = l0.u;
                *(uint32_t*)(Ch + (size_t)r1 * N + col) = h1.u;
                *(uint32_t*)(Cl + (size_t)r1 * N + col) = l1.u;
            } else {
                *(float2*)(Cf + (size_t)r0 * N + col) = make_float2(v0, v1);
                *(float2*)(Cf + (size_t)r1 * N + col) = make_float2(v2, v3);
            }
        }
    }
}

// ---------------- attention prep ----------------
__global__ __launch_bounds__(256) void attnprep_kernel(
    const float* __restrict__ qkv,
    __nv_bfloat16* __restrict__ Qh, __nv_bfloat16* __restrict__ Ql,
    __nv_bfloat16* __restrict__ Kh, __nv_bfloat16* __restrict__ Kl,
    __nv_bfloat16* __restrict__ Vth, __nv_bfloat16* __restrict__ Vtl)
{
    __shared__ float vs[64][65];
    int tb = blockIdx.x, bh = blockIdx.y;
    int b = bh >> 4, hd = bh & 15;
    int t0 = tb * 64;
    int tid = threadIdx.x;

    for (int i = tid; i < 1024; i += 256) {
        int r = i >> 4, c4 = (i & 15) * 4;
        const float* base = qkv + ((size_t)(b * TT + t0 + r)) * (3 * CEMB) + hd * HS + c4;
        float4 q = *(const float4*)base;
        float4 k = *(const float4*)(base + CEMB);
        float4 v = *(const float4*)(base + 2 * CEMB);
        float qa[4] = {q.x * 0.125f, q.y * 0.125f, q.z * 0.125f, q.w * 0.125f};
        float ka[4] = {k.x, k.y, k.z, k.w};
        P4 ph, pl;
        size_t qo = ((size_t)bh * TT + t0 + r) * HS + c4;
        split4(qa, ph, pl);
        *(uint2*)(Qh + qo) = ph.u; *(uint2*)(Ql + qo) = pl.u;
        split4(ka, ph, pl);
        *(uint2*)(Kh + qo) = ph.u; *(uint2*)(Kl + qo) = pl.u;
        vs[r][c4] = v.x; vs[r][c4+1] = v.y; vs[r][c4+2] = v.z; vs[r][c4+3] = v.w;
    }
    __syncthreads();
    for (int i = tid; i < 1024; i += 256) {
        int d = i >> 4, tq = (i & 15) * 4;
        float vv[4] = { vs[tq+0][d], vs[tq+1][d], vs[tq+2][d], vs[tq+3][d] };
        P4 ph, pl;
        split4(vv, ph, pl);
        size_t vo = ((size_t)bh * HS + d) * TT + t0 + tq;
        *(uint2*)(Vth + vo) = ph.u; *(uint2*)(Vtl + vo) = pl.u;
    }
}

// ---------------- HMMA flash attention ----------------
#define ATSM_BUF(b) (32768 + (b) * 32768)
#define ATSM_P 98304
#define ATT_SMEM (131072 + 1024)

__global__ __launch_bounds__(256, 1) void attn_mma_kernel(
    const __nv_bfloat16* __restrict__ Qh_, const __nv_bfloat16* __restrict__ Ql_,
    const __nv_bfloat16* __restrict__ Kh_, const __nv_bfloat16* __restrict__ Kl_,
    const __nv_bfloat16* __restrict__ Vth_, const __nv_bfloat16* __restrict__ Vtl_,
    __nv_bfloat16* __restrict__ yh, __nv_bfloat16* __restrict__ yl)
{
    extern __shared__ char dsm[];
    uintptr_t pa = ((uintptr_t)dsm + 1023) & ~(uintptr_t)1023;
    uint32_t sb = smem_u32((char*)pa);

    int qt = gridDim.x - 1 - blockIdx.x;
    int q0 = qt * 128;
    int bh = blockIdx.y;
    int b = bh >> 4, hd = bh & 15;
    size_t hq = (size_t)bh * TT * HS;

    int tid = threadIdx.x;
    int wid = tid >> 5, lid = tid & 31;
    int lrow16 = lid & 15, khalf = lid >> 4;
    int arow = wid * 16 + lrow16;

    auto load_kv = [&](int jb, int buf) {
        int j0 = jb * 64;
        uint32_t st = sb + ATSM_BUF(buf);
        const char* kh = (const char*)(Kh_ + hq + (size_t)j0 * HS);
        const char* kl = (const char*)(Kl_ + hq + (size_t)j0 * HS);
        const char* vh = (const char*)(Vth_ + hq) + (size_t)j0 * 2;
        const char* vl = (const char*)(Vtl_ + hq) + (size_t)j0 * 2;
        #pragma unroll
        for (int i = tid; i < 512; i += 256) {
            int row = i >> 3, ch = i & 7;
            uint32_t so = sw128((uint32_t)(row * 128 + ch * 16));
            CP_ASYNC16(st + so,         kh + row * 128 + ch * 16);
            CP_ASYNC16(st + 8192 + so,  kl + row * 128 + ch * 16);
            CP_ASYNC16(st + 16384 + so, vh + (size_t)row * (TT * 2) + ch * 16);
            CP_ASYNC16(st + 24576 + so, vl + (size_t)row * (TT * 2) + ch * 16);
        }
    };

    {
        const char* qh = (const char*)(Qh_ + hq + (size_t)q0 * HS);
        const char* ql = (const char*)(Ql_ + hq + (size_t)q0 * HS);
        #pragma unroll
        for (int i = tid; i < 1024; i += 256) {
            int row = i >> 3, ch = i & 7;
            uint32_t so = sw128((uint32_t)(row * 128 + ch * 16));
            CP_ASYNC16(sb + so,         qh + row * 128 + ch * 16);
            CP_ASYNC16(sb + 16384 + so, ql + row * 128 + ch * 16);
        }
    }
    load_kv(0, 0);
    CP_COMMIT();

    float m_[2] = {-INFINITY, -INFINITY};
    float l_[2] = {0.f, 0.f};
    float acc[8][4];
    #pragma unroll
    for (int nb = 0; nb < 8; nb++)
        #pragma unroll
        for (int q = 0; q < 4; q++) acc[nb][q] = 0.f;

    int jbmax = q0 / 64 + 1;
    for (int jb = 0; jb <= jbmax; jb++) {
        int buf = jb & 1;
        CP_WAIT0();
        __syncthreads();
        if (jb < jbmax) { load_kv(jb + 1, buf ^ 1); CP_COMMIT(); }

        uint32_t sK = sb + ATSM_BUF(buf);
        uint32_t sV = sK + 16384;

        float s[8][4];
        #pragma unroll
        for (int nb = 0; nb < 8; nb++)
            #pragma unroll
            for (int q = 0; q < 4; q++) s[nb][q] = 0.f;

        #pragma unroll
        for (int ks = 0; ks < 4; ks++) {
            int ach = (ks * 2 + khalf) ^ (arow & 7);
            uint32_t aa = sb + (uint32_t)(arow * 128 + ach * 16);
            uint32_t aH[4], aL[4];
            LDSM_X4(aH[0], aH[1], aH[2], aH[3], aa);
            LDSM_X4(aL[0], aL[1], aL[2], aL[3], aa + 16384);
            uint32_t bH[4][4], bL[4][4];
            #pragma unroll
            for (int nb2 = 0; nb2 < 4; nb2++) {
                int br = nb2 * 16 + lrow16;
                int bch = (ks * 2 + khalf) ^ (br & 7);
                uint32_t ba = sK + (uint32_t)(br * 128 + bch * 16);
                LDSM_X4(bH[nb2][0], bH[nb2][1], bH[nb2][2], bH[nb2][3], ba);
                LDSM_X4(bL[nb2][0], bL[nb2][1], bL[nb2][2], bL[nb2][3], ba + 8192);
            }
            #pragma unroll
            for (int nb2 = 0; nb2 < 4; nb2++) {
                MMA16816(s[nb2*2],   aH, bH[nb2][0], bH[nb2][2]);
                MMA16816(s[nb2*2],   aH, bL[nb2][0], bL[nb2][2]);
                MMA16816(s[nb2*2],   aL, bH[nb2][0], bH[nb2][2]);
                MMA16816(s[nb2*2+1], aH, bH[nb2][1], bH[nb2][3]);
                MMA16816(s[nb2*2+1], aH, bL[nb2][1], bL[nb2][3]);
                MMA16816(s[nb2*2+1], aL, bH[nb2][1], bH[nb2][3]);
            }
        }

        int j0 = jb * 64;
        if (j0 + 63 > q0 + wid * 16) {
            int r0g = q0 + wid * 16 + (lid >> 2);
            #pragma unroll
            for (int nb = 0; nb < 8; nb++) {
                int c0 = j0 + nb * 8 + (lid & 3) * 2;
                if (c0     > r0g)     s[nb][0] = -INFINITY;
                if (c0 + 1 > r0g)     s[nb][1] = -INFINITY;
                if (c0     > r0g + 8) s[nb][2] = -INFINITY;
                if (c0 + 1 > r0g + 8) s[nb][3] = -INFINITY;
            }
        }

        float rmax[2] = {-INFINITY, -INFINITY};
        #pragma unroll
        for (int nb = 0; nb < 8; nb++) {
            rmax[0] = fmaxf(rmax[0], fmaxf(s[nb][0], s[nb][1]));
            rmax[1] = fmaxf(rmax[1], fmaxf(s[nb][2], s[nb][3]));
        }
        #pragma unroll
        for (int o = 1; o <= 2; o <<= 1) {
            rmax[0] = fmaxf(rmax[0], __shfl_xor_sync(0xffffffffu, rmax[0], o));
            rmax[1] = fmaxf(rmax[1], __shfl_xor_sync(0xffffffffu, rmax[1], o));
        }
        float mn0 = fmaxf(m_[0], rmax[0]);
        float mn1 = fmaxf(m_[1], rmax[1]);
        float alpha0 = __expf(m_[0] - mn0);
        float alpha1 = __expf(m_[1] - mn1);
        m_[0] = mn0; m_[1] = mn1;
        float rs[2] = {0.f, 0.f};
        #pragma unroll
        for (int nb = 0; nb < 8; nb++) {
            s[nb][0] = __expf(s[nb][0] - mn0); rs[0] += s[nb][0];
            s[nb][1] = __expf(s[nb][1] - mn0); rs[0] += s[nb][1];
            s[nb][2] = __expf(s[nb][2] - mn1); rs[1] += s[nb][2];
            s[nb][3] = __expf(s[nb][3] - mn1); rs[1] += s[nb][3];
        }
        #pragma unroll
        for (int o = 1; o <= 2; o <<= 1) {
            rs[0] += __shfl_xor_sync(0xffffffffu, rs[0], o);
            rs[1] += __shfl_xor_sync(0xffffffffu, rs[1], o);
        }
        l_[0] = l_[0] * alpha0 + rs[0];
        l_[1] = l_[1] * alpha1 + rs[1];
        #pragma unroll
        for (int nb = 0; nb < 8; nb++) {
            acc[nb][0] *= alpha0; acc[nb][1] *= alpha0;
            acc[nb][2] *= alpha1; acc[nb][3] *= alpha1;
        }

        {
            int r0 = wid * 16 + (lid >> 2);
            #pragma unroll
            for (int nb = 0; nb < 8; nb++) {
                int coff = (nb * 8 + (lid & 3) * 2) * 2;
                uint32_t o0 = sw128((uint32_t)(r0 * 128 + coff));
                uint32_t o1 = sw128((uint32_t)((r0 + 8) * 128 + coff));
                P2 h, l2;
                split2(s[nb][0], s[nb][1], h, l2);
                STS32(sb + ATSM_P + o0, h.u);
                STS32(sb + ATSM_P + 16384 + o0, l2.u);
                split2(s[nb][2], s[nb][3], h, l2);
                STS32(sb + ATSM_P + o1, h.u);
                STS32(sb + ATSM_P + 16384 + o1, l2.u);
            }
        }
        __syncwarp();

        #pragma unroll
        for (int ks = 0; ks < 4; ks++) {
            int ach = (ks * 2 + khalf) ^ (arow & 7);
            uint32_t paddr = sb + ATSM_P + (uint32_t)(arow * 128 + ach * 16);
            uint32_t pH[4], pL[4];
            LDSM_X4(pH[0], pH[1], pH[2], pH[3], paddr);
            LDSM_X4(pL[0], pL[1], pL[2], pL[3], paddr + 16384);
            uint32_t bH[4][4], bL[4][4];
            #pragma unroll
            for (int nb2 = 0; nb2 < 4; nb2++) {
                int br = nb2 * 16 + lrow16;
                int bch = (ks * 2 + khalf) ^ (br & 7);
                uint32_t ba = sV + (uint32_t)(br * 128 + bch * 16);
                LDSM_X4(bH[nb2][0], bH[nb2][1], bH[nb2][2], bH[nb2][3], ba);
                LDSM_X4(bL[nb2][0], bL[nb2][1], bL[nb2][2], bL[nb2][3], ba + 8192);
            }
            #pragma unroll
            for (int nb2 = 0; nb2 < 4; nb2++) {
                MMA16816(acc[nb2*2],   pH, bH[nb2][0], bH[nb2][2]);
                MMA16816(acc[nb2*2],   pH, bL[nb2][0], bL[nb2][2]);
                MMA16816(acc[nb2*2],   pL, bH[nb2][0], bH[nb2][2]);
                MMA16816(acc[nb2*2+1], pH, bH[nb2][1], bH[nb2][3]);
                MMA16816(acc[nb2*2+1], pH, bL[nb2][1], bL[nb2][3]);
                MMA16816(acc[nb2*2+1], pL, bH[nb2][1], bH[nb2][3]);
            }
        }
    }

    float inv0 = 1.0f / l_[0];
    float inv1 = 1.0f / l_[1];
    size_t r0g = (size_t)b * TT + q0 + wid * 16 + (lid >> 2);
    #pragma unroll
    for (int nb = 0; nb < 8; nb++) {
        int col = hd * HS + nb * 8 + (lid & 3) * 2;
        P2 h, l2;
        split2(acc[nb][0] * inv0, acc[nb][1] * inv0, h, l2);
        *(uint32_t*)(yh + r0g * CEMB + col) = h.u;
        *(uint32_t*)(yl + r0g * CEMB + col) = l2.u;
        split2(acc[nb][2] * inv1, acc[nb][3] * inv1, h, l2);
        *(uint32_t*)(yh + (r0g + 8) * CEMB + col) = h.u;
        *(uint32_t*)(yl + (r0g + 8) * CEMB + col) = l2.u;
    }
}

// ---------------- launch ----------------
extern "C" void kernel_launch(void* const* d_in, const int* in_sizes, int n_in,
                              void* d_out, int out_size)
{
    const float* x      = (const float*)d_in[0];
    const float* ln1_g  = (const float*)d_in[1];
    const float* ln1_b  = (const float*)d_in[2];
    const float* w_attn = (const float*)d_in[3];
    const float* b_attn = (const float*)d_in[4];
    const float* w_proj = (const float*)d_in[5];
    const float* b_proj = (const float*)d_in[6];
    const float* ln2_g  = (const float*)d_in[7];
    const float* ln2_b  = (const float*)d_in[8];
    const float* w_fc   = (const float*)d_in[9];
    const float* b_fc   = (const float*)d_in[10];
    const float* w_fc2  = (const float*)d_in[11];
    const float* b_fc2  = (const float*)d_in[12];
    float* out = (float*)d_out;

    float *qkv, *x2;
    __nv_bfloat16 *hh, *hl, *yh, *yl, *fh, *fl;
    __nv_bfloat16 *wah, *wal, *wph, *wpl, *wfh, *wfl, *w2h, *w2l;
    __nv_bfloat16 *aqh, *aql, *akh, *akl, *avh, *avl;
    cudaGetSymbolAddress((void**)&qkv, g_qkv);
    cudaGetSymbolAddress((void**)&x2,  g_x2);
    cudaGetSymbolAddress((void**)&hh,  g_hh);
    cudaGetSymbolAddress((void**)&hl,  g_hl);
    cudaGetSymbolAddress((void**)&yh,  g_yh);
    cudaGetSymbolAddress((void**)&yl,  g_yl);
    cudaGetSymbolAddress((void**)&fh,  g_fh);
    cudaGetSymbolAddress((void**)&fl,  g_fl);
    cudaGetSymbolAddress((void**)&wah, g_wah);
    cudaGetSymbolAddress((void**)&wal, g_wal);
    cudaGetSymbolAddress((void**)&wph, g_wph);
    cudaGetSymbolAddress((void**)&wpl, g_wpl);
    cudaGetSymbolAddress((void**)&wfh, g_wfh);
    cudaGetSymbolAddress((void**)&wfl, g_wfl);
    cudaGetSymbolAddress((void**)&w2h, g_w2h);
    cudaGetSymbolAddress((void**)&w2l, g_w2l);
    cudaGetSymbolAddress((void**)&aqh, g_aqh);
    cudaGetSymbolAddress((void**)&aql, g_aql);
    cudaGetSymbolAddress((void**)&akh, g_akh);
    cudaGetSymbolAddress((void**)&akl, g_akl);
    cudaGetSymbolAddress((void**)&avh, g_avh);
    cudaGetSymbolAddress((void**)&avl, g_avl);

    cudaFuncSetAttribute(gemm_bf16x3<0>, cudaFuncAttributeMaxDynamicSharedMemorySize, SMEM_GEMM);
    cudaFuncSetAttribute(gemm_bf16x3<1>, cudaFuncAttributeMaxDynamicSharedMemorySize, SMEM_GEMM);
    cudaFuncSetAttribute(gemm_bf16x3<2>, cudaFuncAttributeMaxDynamicSharedMemorySize, SMEM_GEMM);
    cudaFuncSetAttribute(attn_mma_kernel, cudaFuncAttributeMaxDynamicSharedMemorySize, ATT_SMEM);

    dim3 blk(256);

    wsplit_kernel<<<dim3(3*CEMB/32, CEMB/32), blk>>>(w_attn, wah, wal, CEMB, 3*CEMB);
    wsplit_kernel<<<dim3(CEMB/32,   CEMB/32), blk>>>(w_proj, wph, wpl, CEMB, CEMB);
    wsplit_kernel<<<dim3(DFF/32,    CEMB/32), blk>>>(w_fc,   wfh, wfl, CEMB, DFF);
    wsplit_kernel<<<dim3(CEMB/32,   DFF/32),  blk>>>(w_fc2,  w2h, w2l, DFF,  CEMB);

    ln_kernel<<<MROWS, blk>>>(x, ln1_g, ln1_b, hh, hl);
    gemm_bf16x3<0><<<dim3(3*CEMB/BN, MROWS/BM), GT, SMEM_GEMM>>>(
        hh, hl, wah, wal, b_attn, nullptr, qkv, nullptr, nullptr, MROWS, 3*CEMB, CEMB);
    attnprep_kernel<<<dim3(TT/64, BB*NHEADS), blk>>>(qkv, aqh, aql, akh, akl, avh, avl);
    attn_mma_kernel<<<dim3(TT/128, BB*NHEADS), blk, ATT_SMEM>>>(
        aqh, aql, akh, akl, avh, avl, yh, yl);
    gemm_bf16x3<1><<<dim3(CEMB/BN, MROWS/BM), GT, SMEM_GEMM>>>(
        yh, yl, wph, wpl, b_proj, x, x2, nullptr, nullptr, MROWS, CEMB, CEMB);
    ln_kernel<<<MROWS, blk>>>(x2, ln2_g, ln2_b, hh, hl);
    gemm_bf16x3<2><<<dim3(DFF/BN, MROWS/BM), GT, SMEM_GEMM>>>(
        hh, hl, wfh, wfl, b_fc, nullptr, nullptr, fh, fl, MROWS, DFF, CEMB);
    gemm_bf16x3<1><<<dim3(CEMB/BN, MROWS/BM), GT, SMEM_GEMM>>>(
        fh, fl, w2h, w2l, b_fc2, x2, out, nullptr, nullptr, MROWS, CEMB, DFF);
}

// round 5
// speedup vs baseline: 4.0791x; 1.4711x over previous
#include <cuda_runtime.h>
#include <cuda_fp16.h>
#include <math.h>
#include <stdint.h>

#define CEMB 1024
#define NHEADS 16
#define HS 64
#define DFF 4096
#define BB 4
#define TT 2048
#define MROWS (BB*TT)   // 8192

#define BM 128
#define BN 128
#define BKE 64
#define GT 256

// ---------------- scratch ----------------
__device__ float g_qkv[(size_t)MROWS * 3 * CEMB];
__device__ float g_x2 [(size_t)MROWS * CEMB];
__device__ __half g_hh[(size_t)MROWS * CEMB];       // ln out hi
__device__ __half g_hl[(size_t)MROWS * CEMB];       // ln out lo
__device__ __half g_yh[(size_t)MROWS * CEMB];       // attn out hi
__device__ __half g_yl[(size_t)MROWS * CEMB];       // attn out lo
__device__ __half g_fh[(size_t)MROWS * DFF];        // mlp hidden hi
__device__ __half g_fl[(size_t)MROWS * DFF];        // mlp hidden lo
// weights, transposed to [N,K] K-major, single fp16
__device__ __half g_wa[(size_t)3*CEMB * CEMB];
__device__ __half g_wp[(size_t)CEMB * CEMB];
__device__ __half g_wf[(size_t)DFF * CEMB];
__device__ __half g_w2[(size_t)CEMB * DFF];
// attention operands
__device__ __half g_aqh[(size_t)64 * TT * HS];
__device__ __half g_aql[(size_t)64 * TT * HS];
__device__ __half g_ak [(size_t)64 * TT * HS];
__device__ __half g_av [(size_t)64 * HS * TT];      // V transposed [bh][d][t]

// ---------------- PTX helpers ----------------
__device__ __forceinline__ uint32_t smem_u32(const void* p) {
    uint32_t a;
    asm("{ .reg .u64 t; cvta.to.shared.u64 t, %1; cvt.u32.u64 %0, t; }" : "=r"(a) : "l"(p));
    return a;
}
#define CP_ASYNC16(s, g) \
    asm volatile("cp.async.cg.shared.global [%0], [%1], 16;" :: "r"(s), "l"(g) : "memory")
#define CP_COMMIT() asm volatile("cp.async.commit_group;" ::: "memory")
#define CP_WAIT1()  asm volatile("cp.async.wait_group 1;" ::: "memory")
#define CP_WAIT0()  asm volatile("cp.async.wait_group 0;" ::: "memory")
#define LDSM_X4(r0, r1, r2, r3, addr) \
    asm volatile("ldmatrix.sync.aligned.m8n8.x4.shared.b16 {%0,%1,%2,%3}, [%4];" \
        : "=r"(r0), "=r"(r1), "=r"(r2), "=r"(r3) : "r"(addr))
#define MMAF16(c, a, b0v, b1v) \
    asm volatile("mma.sync.aligned.m16n8k16.row.col.f32.f16.f16.f32 " \
        "{%0,%1,%2,%3}, {%4,%5,%6,%7}, {%8,%9}, {%0,%1,%2,%3};" \
        : "+f"((c)[0]), "+f"((c)[1]), "+f"((c)[2]), "+f"((c)[3]) \
        : "r"((a)[0]), "r"((a)[1]), "r"((a)[2]), "r"((a)[3]), "r"(b0v), "r"(b1v))
#define STS32(addr, v) \
    asm volatile("st.shared.b32 [%0], %1;" :: "r"(addr), "r"(v) : "memory")

__device__ __forceinline__ uint32_t sw128(uint32_t off) { return off ^ ((off >> 3) & 0x70); }

__device__ __forceinline__ float gelu_f(float x) {
    float t = tanhf(0.79788456080286536f * (x + 0.044715f * x * x * x));
    return 0.5f * x * (1.0f + t);
}

union H4 { __half h[4]; uint2 u; };
__device__ __forceinline__ void split4h(const float* v, H4& ph, H4& pl) {
    #pragma unroll
    for (int j = 0; j < 4; j++) {
        __half hb = __float2half(v[j]);
        ph.h[j] = hb;
        pl.h[j] = __float2half(v[j] - __half2float(hb));
    }
}
union H2 { __half h[2]; uint32_t u; };
__device__ __forceinline__ void split2h(float v0, float v1, H2& h, H2& l) {
    h.h[0] = __float2half(v0);
    l.h[0] = __float2half(v0 - __half2float(h.h[0]));
    h.h[1] = __float2half(v1);
    l.h[1] = __float2half(v1 - __half2float(h.h[1]));
}

// ---------------- weight transpose + fp16 convert ----------------
__global__ __launch_bounds__(256) void wconv_kernel(const float* __restrict__ W,
    __half* __restrict__ Wf, int K, int N)
{
    __shared__ float t[32][33];
    int n0 = blockIdx.x * 32, k0 = blockIdx.y * 32;
    int tx = threadIdx.x & 31, ty = threadIdx.x >> 5;
    #pragma unroll
    for (int r = ty; r < 32; r += 8)
        t[r][tx] = W[(size_t)(k0 + r) * N + n0 + tx];
    __syncthreads();
    #pragma unroll
    for (int r = ty; r < 32; r += 8)
        Wf[(size_t)(n0 + r) * K + k0 + tx] = __float2half(t[tx][r]);
}

// ---------------- LayerNorm -> split fp16 ----------------
__global__ __launch_bounds__(256) void ln_kernel(const float* __restrict__ x,
                                                 const float* __restrict__ g,
                                                 const float* __restrict__ b,
                                                 __half* __restrict__ oh,
                                                 __half* __restrict__ ol)
{
    int row = blockIdx.x;
    int t = threadIdx.x;
    float4 v = ((const float4*)(x + (size_t)row * CEMB))[t];
    float s  = v.x + v.y + v.z + v.w;
    float ss = v.x*v.x + v.y*v.y + v.z*v.z + v.w*v.w;
    #pragma unroll
    for (int o = 16; o > 0; o >>= 1) {
        s  += __shfl_xor_sync(0xffffffffu, s,  o);
        ss += __shfl_xor_sync(0xffffffffu, ss, o);
    }
    __shared__ float red[16];
    int warp = t >> 5, lane = t & 31;
    if (lane == 0) { red[warp] = s; red[warp + 8] = ss; }
    __syncthreads();
    float sum = 0.f, sumsq = 0.f;
    #pragma unroll
    for (int w = 0; w < 8; w++) { sum += red[w]; sumsq += red[w + 8]; }
    float mu   = sum * (1.0f / CEMB);
    float var  = sumsq * (1.0f / CEMB) - mu * mu;
    float rstd = rsqrtf(var + 1e-5f);
    float4 gv = ((const float4*)g)[t];
    float4 bv = ((const float4*)b)[t];
    float o[4];
    o[0] = (v.x - mu) * rstd * gv.x + bv.x;
    o[1] = (v.y - mu) * rstd * gv.y + bv.y;
    o[2] = (v.z - mu) * rstd * gv.z + bv.z;
    o[3] = (v.w - mu) * rstd * gv.w + bv.w;
    H4 ph, pl;
    split4h(o, ph, pl);
    *(uint2*)(oh + (size_t)row * CEMB + t * 4) = ph.u;
    *(uint2*)(ol + (size_t)row * CEMB + t * 4) = pl.u;
}

// ---------------- HMMA fp16 GEMM: C = (Ah+Al) @ B^T + bias ----------------
// A split fp16 hi/lo, B single fp16. 2 MMAs per product.
// stage: Ah 16K | Al 16K | B 16K = 48KB, double buffered -> 96KB, 2 CTAs/SM.
#define STAGE_BYTES 49152
#define SMEM_GEMM (2 * STAGE_BYTES + 1024)

template<int EPI>
__global__ __launch_bounds__(GT, 2) void gemm_f16x2(
    const __half* __restrict__ Ah, const __half* __restrict__ Al,
    const __half* __restrict__ Bf,
    const float* __restrict__ bias, const float* __restrict__ R,
    float* __restrict__ Cf, __half* __restrict__ Ch, __half* __restrict__ Cl,
    int M, int N, int K)
{
    extern __shared__ char dsm[];
    uintptr_t pa = ((uintptr_t)dsm + 1023) & ~(uintptr_t)1023;
    uint32_t sb = smem_u32((char*)pa);

    int tid = threadIdx.x;
    int wid = tid >> 5, lid = tid & 31;
    int wm = wid >> 1, wn = wid & 1;
    int m0 = blockIdx.y * BM, n0 = blockIdx.x * BN;

    const int NC = K / BKE;
    int lrow = tid >> 3;
    int lch  = tid & 7;

    auto load_stage = [&](int c) {
        int buf = c & 1;
        uint32_t st = sb + buf * STAGE_BYTES;
        int k0 = c * BKE;
        #pragma unroll
        for (int t = 0; t < 4; t++) {
            int row = lrow + t * 32;
            uint32_t so = sw128((uint32_t)(row * 128 + lch * 16));
            size_t ga = (size_t)(m0 + row) * K + k0 + lch * 8;
            CP_ASYNC16(st + so,         (const char*)(Ah + ga));
            CP_ASYNC16(st + 16384 + so, (const char*)(Al + ga));
            size_t gb = (size_t)(n0 + row) * K + k0 + lch * 8;
            CP_ASYNC16(st + 32768 + so, (const char*)(Bf + gb));
        }
    };

    float acc[2][8][4];
    #pragma unroll
    for (int mi = 0; mi < 2; mi++)
        #pragma unroll
        for (int j = 0; j < 8; j++)
            #pragma unroll
            for (int q = 0; q < 4; q++) acc[mi][j][q] = 0.f;

    int lrow16 = lid & 15;
    int khalf  = lid >> 4;

    load_stage(0);
    CP_COMMIT();

    for (int c = 0; c < NC; c++) {
        if (c + 1 < NC) { load_stage(c + 1); CP_COMMIT(); CP_WAIT1(); }
        else            { CP_WAIT0(); }
        __syncthreads();

        uint32_t st = sb + (c & 1) * STAGE_BYTES;

        #pragma unroll
        for (int s = 0; s < 4; s++) {
            uint32_t aH[2][4], aL[2][4], bH[4][4];
            #pragma unroll
            for (int mi = 0; mi < 2; mi++) {
                int row = wm * 32 + mi * 16 + lrow16;
                int ch = (s * 2 + khalf) ^ (row & 7);
                uint32_t ad = st + (uint32_t)(row * 128 + ch * 16);
                LDSM_X4(aH[mi][0], aH[mi][1], aH[mi][2], aH[mi][3], ad);
                LDSM_X4(aL[mi][0], aL[mi][1], aL[mi][2], aL[mi][3], ad + 16384);
            }
            #pragma unroll
            for (int nb = 0; nb < 4; nb++) {
                int row = wn * 64 + nb * 16 + lrow16;
                int ch = (s * 2 + khalf) ^ (row & 7);
                uint32_t bd = st + 32768 + (uint32_t)(row * 128 + ch * 16);
                LDSM_X4(bH[nb][0], bH[nb][1], bH[nb][2], bH[nb][3], bd);
            }
            #pragma unroll
            for (int mi = 0; mi < 2; mi++) {
                #pragma unroll
                for (int nb = 0; nb < 4; nb++) {
                    MMAF16(acc[mi][nb*2],   aH[mi], bH[nb][0], bH[nb][2]);
                    MMAF16(acc[mi][nb*2],   aL[mi], bH[nb][0], bH[nb][2]);
                    MMAF16(acc[mi][nb*2+1], aH[mi], bH[nb][1], bH[nb][3]);
                    MMAF16(acc[mi][nb*2+1], aL[mi], bH[nb][1], bH[nb][3]);
                }
            }
        }
        __syncthreads();
    }

    int gid = lid >> 2, tig = lid & 3;
    #pragma unroll
    for (int mi = 0; mi < 2; mi++) {
        #pragma unroll
        for (int j = 0; j < 8; j++) {
            int r0 = m0 + wm * 32 + mi * 16 + gid;
            int r1 = r0 + 8;
            int col = n0 + wn * 64 + j * 8 + tig * 2;
            float b0 = bias[col], b1 = bias[col + 1];
            float v0 = acc[mi][j][0] + b0, v1 = acc[mi][j][1] + b1;
            float v2 = acc[mi][j][2] + b0, v3 = acc[mi][j][3] + b1;
            if (EPI == 1) {
                float2 q0 = *(const float2*)(R + (size_t)r0 * N + col);
                float2 q1 = *(const float2*)(R + (size_t)r1 * N + col);
                v0 += q0.x; v1 += q0.y; v2 += q1.x; v3 += q1.y;
            }
            if (EPI == 2) {
                v0 = gelu_f(v0); v1 = gelu_f(v1); v2 = gelu_f(v2); v3 = gelu_f(v3);
                H2 h0, l0, h1, l1;
                split2h(v0, v1, h0, l0);
                split2h(v2, v3, h1, l1);
                *(uint32_t*)(Ch + (size_t)r0 * N + col) = h0.u;
                *(uint32_t*)(Cl + (size_t)r0 * N + col) = l0.u;
                *(uint32_t*)(Ch + (size_t)r1 * N + col) = h1.u;
                *(uint32_t*)(Cl + (size_t)r1 * N + col) = l1.u;
            } else {
                *(float2*)(Cf + (size_t)r0 * N + col) = make_float2(v0, v1);
                *(float2*)(Cf + (size_t)r1 * N + col) = make_float2(v2, v3);
            }
        }
    }
}

// ---------------- attention prep ----------------
__global__ __launch_bounds__(256) void attnprep_kernel(
    const float* __restrict__ qkv,
    __half* __restrict__ Qh, __half* __restrict__ Ql,
    __half* __restrict__ Kf, __half* __restrict__ Vt)
{
    __shared__ float vs[64][65];
    int tb = blockIdx.x, bh = blockIdx.y;
    int b = bh >> 4, hd = bh & 15;
    int t0 = tb * 64;
    int tid = threadIdx.x;

    for (int i = tid; i < 1024; i += 256) {
        int r = i >> 4, c4 = (i & 15) * 4;
        const float* base = qkv + ((size_t)(b * TT + t0 + r)) * (3 * CEMB) + hd * HS + c4;
        float4 q = *(const float4*)base;
        float4 k = *(const float4*)(base + CEMB);
        float4 v = *(const float4*)(base + 2 * CEMB);
        float qa[4] = {q.x * 0.125f, q.y * 0.125f, q.z * 0.125f, q.w * 0.125f};
        H4 ph, pl;
        size_t qo = ((size_t)bh * TT + t0 + r) * HS + c4;
        split4h(qa, ph, pl);
        *(uint2*)(Qh + qo) = ph.u; *(uint2*)(Ql + qo) = pl.u;
        H4 kk;
        kk.h[0] = __float2half(k.x); kk.h[1] = __float2half(k.y);
        kk.h[2] = __float2half(k.z); kk.h[3] = __float2half(k.w);
        *(uint2*)(Kf + qo) = kk.u;
        vs[r][c4] = v.x; vs[r][c4+1] = v.y; vs[r][c4+2] = v.z; vs[r][c4+3] = v.w;
    }
    __syncthreads();
    for (int i = tid; i < 1024; i += 256) {
        int d = i >> 4, tq = (i & 15) * 4;
        H4 vv;
        vv.h[0] = __float2half(vs[tq+0][d]);
        vv.h[1] = __float2half(vs[tq+1][d]);
        vv.h[2] = __float2half(vs[tq+2][d]);
        vv.h[3] = __float2half(vs[tq+3][d]);
        size_t vo = ((size_t)bh * HS + d) * TT + t0 + tq;
        *(uint2*)(Vt + vo) = vv.u;
    }
}

// ---------------- HMMA flash attention (fp16, Q/P split, K/V single) ----------------
// smem: Qh 0 | Ql 16K | buf(b) @32K+16K*b: K 8K, Vt 8K | Ph 64K | Pl 80K = 96KB
#define ATSM_BUF(b) (32768 + (b) * 16384)
#define ATSM_P 65536
#define ATT_SMEM (98304 + 1024)

__global__ __launch_bounds__(256, 1) void attn_mma_kernel(
    const __half* __restrict__ Qh_, const __half* __restrict__ Ql_,
    const __half* __restrict__ Kf_, const __half* __restrict__ Vt_,
    __half* __restrict__ yh, __half* __restrict__ yl)
{
    extern __shared__ char dsm[];
    uintptr_t pa = ((uintptr_t)dsm + 1023) & ~(uintptr_t)1023;
    uint32_t sb = smem_u32((char*)pa);

    int qt = gridDim.x - 1 - blockIdx.x;
    int q0 = qt * 128;
    int bh = blockIdx.y;
    int b = bh >> 4, hd = bh & 15;
    size_t hq = (size_t)bh * TT * HS;

    int tid = threadIdx.x;
    int wid = tid >> 5, lid = tid & 31;
    int lrow16 = lid & 15, khalf = lid >> 4;
    int arow = wid * 16 + lrow16;

    auto load_kv = [&](int jb, int buf) {
        int j0 = jb * 64;
        uint32_t st = sb + ATSM_BUF(buf);
        const char* kf = (const char*)(Kf_ + hq + (size_t)j0 * HS);
        const char* vt = (const char*)(Vt_ + hq) + (size_t)j0 * 2;
        #pragma unroll
        for (int i = tid; i < 512; i += 256) {
            int row = i >> 3, ch = i & 7;
            uint32_t so = sw128((uint32_t)(row * 128 + ch * 16));
            CP_ASYNC16(st + so,        kf + row * 128 + ch * 16);
            CP_ASYNC16(st + 8192 + so, vt + (size_t)row * (TT * 2) + ch * 16);
        }
    };

    {
        const char* qh = (const char*)(Qh_ + hq + (size_t)q0 * HS);
        const char* ql = (const char*)(Ql_ + hq + (size_t)q0 * HS);
        #pragma unroll
        for (int i = tid; i < 1024; i += 256) {
            int row = i >> 3, ch = i & 7;
            uint32_t so = sw128((uint32_t)(row * 128 + ch * 16));
            CP_ASYNC16(sb + so,         qh + row * 128 + ch * 16);
            CP_ASYNC16(sb + 16384 + so, ql + row * 128 + ch * 16);
        }
    }
    load_kv(0, 0);
    CP_COMMIT();

    float m_[2] = {-INFINITY, -INFINITY};
    float l_[2] = {0.f, 0.f};
    float acc[8][4];
    #pragma unroll
    for (int nb = 0; nb < 8; nb++)
        #pragma unroll
        for (int q = 0; q < 4; q++) acc[nb][q] = 0.f;

    int jbmax = q0 / 64 + 1;
    for (int jb = 0; jb <= jbmax; jb++) {
        int buf = jb & 1;
        CP_WAIT0();
        __syncthreads();
        if (jb < jbmax) { load_kv(jb + 1, buf ^ 1); CP_COMMIT(); }

        uint32_t sK = sb + ATSM_BUF(buf);
        uint32_t sV = sK + 8192;

        float s[8][4];
        #pragma unroll
        for (int nb = 0; nb < 8; nb++)
            #pragma unroll
            for (int q = 0; q < 4; q++) s[nb][q] = 0.f;

        #pragma unroll
        for (int ks = 0; ks < 4; ks++) {
            int ach = (ks * 2 + khalf) ^ (arow & 7);
            uint32_t aa = sb + (uint32_t)(arow * 128 + ach * 16);
            uint32_t aH[4], aL[4];
            LDSM_X4(aH[0], aH[1], aH[2], aH[3], aa);
            LDSM_X4(aL[0], aL[1], aL[2], aL[3], aa + 16384);
            uint32_t bH[4][4];
            #pragma unroll
            for (int nb2 = 0; nb2 < 4; nb2++) {
                int br = nb2 * 16 + lrow16;
                int bch = (ks * 2 + khalf) ^ (br & 7);
                uint32_t ba = sK + (uint32_t)(br * 128 + bch * 16);
                LDSM_X4(bH[nb2][0], bH[nb2][1], bH[nb2][2], bH[nb2][3], ba);
            }
            #pragma unroll
            for (int nb2 = 0; nb2 < 4; nb2++) {
                MMAF16(s[nb2*2],   aH, bH[nb2][0], bH[nb2][2]);
                MMAF16(s[nb2*2],   aL, bH[nb2][0], bH[nb2][2]);
                MMAF16(s[nb2*2+1], aH, bH[nb2][1], bH[nb2][3]);
                MMAF16(s[nb2*2+1], aL, bH[nb2][1], bH[nb2][3]);
            }
        }

        int j0 = jb * 64;
        if (j0 + 63 > q0 + wid * 16) {
            int r0g = q0 + wid * 16 + (lid >> 2);
            #pragma unroll
            for (int nb = 0; nb < 8; nb++) {
                int c0 = j0 + nb * 8 + (lid & 3) * 2;
                if (c0     > r0g)     s[nb][0] = -INFINITY;
                if (c0 + 1 > r0g)     s[nb][1] = -INFINITY;
                if (c0     > r0g + 8) s[nb][2] = -INFINITY;
                if (c0 + 1 > r0g + 8) s[nb][3] = -INFINITY;
            }
        }

        float rmax[2] = {-INFINITY, -INFINITY};
        #pragma unroll
        for (int nb = 0; nb < 8; nb++) {
            rmax[0] = fmaxf(rmax[0], fmaxf(s[nb][0], s[nb][1]));
            rmax[1] = fmaxf(rmax[1], fmaxf(s[nb][2], s[nb][3]));
        }
        #pragma unroll
        for (int o = 1; o <= 2; o <<= 1) {
            rmax[0] = fmaxf(rmax[0], __shfl_xor_sync(0xffffffffu, rmax[0], o));
            rmax[1] = fmaxf(rmax[1], __shfl_xor_sync(0xffffffffu, rmax[1], o));
        }
        float mn0 = fmaxf(m_[0], rmax[0]);
        float mn1 = fmaxf(m_[1], rmax[1]);
        float alpha0 = __expf(m_[0] - mn0);
        float alpha1 = __expf(m_[1] - mn1);
        m_[0] = mn0; m_[1] = mn1;
        float rs[2] = {0.f, 0.f};
        #pragma unroll
        for (int nb = 0; nb < 8; nb++) {
            s[nb][0] = __expf(s[nb][0] - mn0); rs[0] += s[nb][0];
            s[nb][1] = __expf(s[nb][1] - mn0); rs[0] += s[nb][1];
            s[nb][2] = __expf(s[nb][2] - mn1); rs[1] += s[nb][2];
            s[nb][3] = __expf(s[nb][3] - mn1); rs[1] += s[nb][3];
        }
        #pragma unroll
        for (int o = 1; o <= 2; o <<= 1) {
            rs[0] += __shfl_xor_sync(0xffffffffu, rs[0], o);
            rs[1] += __shfl_xor_sync(0xffffffffu, rs[1], o);
        }
        l_[0] = l_[0] * alpha0 + rs[0];
        l_[1] = l_[1] * alpha1 + rs[1];
        #pragma unroll
        for (int nb = 0; nb < 8; nb++) {
            acc[nb][0] *= alpha0; acc[nb][1] *= alpha0;
            acc[nb][2] *= alpha1; acc[nb][3] *= alpha1;
        }

        {
            int r0 = wid * 16 + (lid >> 2);
            #pragma unroll
            for (int nb = 0; nb < 8; nb++) {
                int coff = (nb * 8 + (lid & 3) * 2) * 2;
                uint32_t o0 = sw128((uint32_t)(r0 * 128 + coff));
                uint32_t o1 = sw128((uint32_t)((r0 + 8) * 128 + coff));
                H2 h, l2;
                split2h(s[nb][0], s[nb][1], h, l2);
                STS32(sb + ATSM_P + o0, h.u);
                STS32(sb + ATSM_P + 16384 + o0, l2.u);
                split2h(s[nb][2], s[nb][3], h, l2);
                STS32(sb + ATSM_P + o1, h.u);
                STS32(sb + ATSM_P + 16384 + o1, l2.u);
            }
        }
        __syncwarp();

        #pragma unroll
        for (int ks = 0; ks < 4; ks++) {
            int ach = (ks * 2 + khalf) ^ (arow & 7);
            uint32_t paddr = sb + ATSM_P + (uint32_t)(arow * 128 + ach * 16);
            uint32_t pH[4], pL[4];
            LDSM_X4(pH[0], pH[1], pH[2], pH[3], paddr);
            LDSM_X4(pL[0], pL[1], pL[2], pL[3], paddr + 16384);
            uint32_t bH[4][4];
            #pragma unroll
            for (int nb2 = 0; nb2 < 4; nb2++) {
                int br = nb2 * 16 + lrow16;
                int bch = (ks * 2 + khalf) ^ (br & 7);
                uint32_t ba = sV + (uint32_t)(br * 128 + bch * 16);
                LDSM_X4(bH[nb2][0], bH[nb2][1], bH[nb2][2], bH[nb2][3], ba);
            }
            #pragma unroll
            for (int nb2 = 0; nb2 < 4; nb2++) {
                MMAF16(acc[nb2*2],   pH, bH[nb2][0], bH[nb2][2]);
                MMAF16(acc[nb2*2],   pL, bH[nb2][0], bH[nb2][2]);
                MMAF16(acc[nb2*2+1], pH, bH[nb2][1], bH[nb2][3]);
                MMAF16(acc[nb2*2+1], pL, bH[nb2][1], bH[nb2][3]);
            }
        }
    }

    float inv0 = 1.0f / l_[0];
    float inv1 = 1.0f / l_[1];
    size_t r0g = (size_t)b * TT + q0 + wid * 16 + (lid >> 2);
    #pragma unroll
    for (int nb = 0; nb < 8; nb++) {
        int col = hd * HS + nb * 8 + (lid & 3) * 2;
        H2 h, l2;
        split2h(acc[nb][0] * inv0, acc[nb][1] * inv0, h, l2);
        *(uint32_t*)(yh + r0g * CEMB + col) = h.u;
        *(uint32_t*)(yl + r0g * CEMB + col) = l2.u;
        split2h(acc[nb][2] * inv1, acc[nb][3] * inv1, h, l2);
        *(uint32_t*)(yh + (r0g + 8) * CEMB + col) = h.u;
        *(uint32_t*)(yl + (r0g + 8) * CEMB + col) = l2.u;
    }
}

// ---------------- launch ----------------
extern "C" void kernel_launch(void* const* d_in, const int* in_sizes, int n_in,
                              void* d_out, int out_size)
{
    const float* x      = (const float*)d_in[0];
    const float* ln1_g  = (const float*)d_in[1];
    const float* ln1_b  = (const float*)d_in[2];
    const float* w_attn = (const float*)d_in[3];
    const float* b_attn = (const float*)d_in[4];
    const float* w_proj = (const float*)d_in[5];
    const float* b_proj = (const float*)d_in[6];
    const float* ln2_g  = (const float*)d_in[7];
    const float* ln2_b  = (const float*)d_in[8];
    const float* w_fc   = (const float*)d_in[9];
    const float* b_fc   = (const float*)d_in[10];
    const float* w_fc2  = (const float*)d_in[11];
    const float* b_fc2  = (const float*)d_in[12];
    float* out = (float*)d_out;

    float *qkv, *x2;
    __half *hh, *hl, *yh, *yl, *fh, *fl;
    __half *wa, *wp, *wf, *w2;
    __half *aqh, *aql, *ak, *av;
    cudaGetSymbolAddress((void**)&qkv, g_qkv);
    cudaGetSymbolAddress((void**)&x2,  g_x2);
    cudaGetSymbolAddress((void**)&hh,  g_hh);
    cudaGetSymbolAddress((void**)&hl,  g_hl);
    cudaGetSymbolAddress((void**)&yh,  g_yh);
    cudaGetSymbolAddress((void**)&yl,  g_yl);
    cudaGetSymbolAddress((void**)&fh,  g_fh);
    cudaGetSymbolAddress((void**)&fl,  g_fl);
    cudaGetSymbolAddress((void**)&wa,  g_wa);
    cudaGetSymbolAddress((void**)&wp,  g_wp);
    cudaGetSymbolAddress((void**)&wf,  g_wf);
    cudaGetSymbolAddress((void**)&w2,  g_w2);
    cudaGetSymbolAddress((void**)&aqh, g_aqh);
    cudaGetSymbolAddress((void**)&aql, g_aql);
    cudaGetSymbolAddress((void**)&ak,  g_ak);
    cudaGetSymbolAddress((void**)&av,  g_av);

    cudaFuncSetAttribute(gemm_f16x2<0>, cudaFuncAttributeMaxDynamicSharedMemorySize, SMEM_GEMM);
    cudaFuncSetAttribute(gemm_f16x2<1>, cudaFuncAttributeMaxDynamicSharedMemorySize, SMEM_GEMM);
    cudaFuncSetAttribute(gemm_f16x2<2>, cudaFuncAttributeMaxDynamicSharedMemorySize, SMEM_GEMM);
    cudaFuncSetAttribute(attn_mma_kernel, cudaFuncAttributeMaxDynamicSharedMemorySize, ATT_SMEM);

    dim3 blk(256);

    wconv_kernel<<<dim3(3*CEMB/32, CEMB/32), blk>>>(w_attn, wa, CEMB, 3*CEMB);
    wconv_kernel<<<dim3(CEMB/32,   CEMB/32), blk>>>(w_proj, wp, CEMB, CEMB);
    wconv_kernel<<<dim3(DFF/32,    CEMB/32), blk>>>(w_fc,   wf, CEMB, DFF);
    wconv_kernel<<<dim3(CEMB/32,   DFF/32),  blk>>>(w_fc2,  w2, DFF,  CEMB);

    ln_kernel<<<MROWS, blk>>>(x, ln1_g, ln1_b, hh, hl);
    gemm_f16x2<0><<<dim3(3*CEMB/BN, MROWS/BM), GT, SMEM_GEMM>>>(
        hh, hl, wa, b_attn, nullptr, qkv, nullptr, nullptr, MROWS, 3*CEMB, CEMB);
    attnprep_kernel<<<dim3(TT/64, BB*NHEADS), blk>>>(qkv, aqh, aql, ak, av);
    attn_mma_kernel<<<dim3(TT/128, BB*NHEADS), blk, ATT_SMEM>>>(
        aqh, aql, ak, av, yh, yl);
    gemm_f16x2<1><<<dim3(CEMB/BN, MROWS/BM), GT, SMEM_GEMM>>>(
        yh, yl, wp, b_proj, x, x2, nullptr, nullptr, MROWS, CEMB, CEMB);
    ln_kernel<<<MROWS, blk>>>(x2, ln2_g, ln2_b, hh, hl);
    gemm_f16x2<2><<<dim3(DFF/BN, MROWS/BM), GT, SMEM_GEMM>>>(
        hh, hl, wf, b_fc, nullptr, nullptr, fh, fl, MROWS, DFF, CEMB);
    gemm_f16x2<1><<<dim3(CEMB/BN, MROWS/BM), GT, SMEM_GEMM>>>(
        fh, fl, w2, b_fc2, x2, out, nullptr, nullptr, MROWS, CEMB, DFF);
}

// round 6
// speedup vs baseline: 7.2417x; 1.7753x over previous
#include <cuda_runtime.h>
#include <cuda_fp16.h>
#include <math.h>
#include <stdint.h>

#define CEMB 1024
#define NHEADS 16
#define HS 64
#define DFF 4096
#define BB 4
#define TT 2048
#define MROWS (BB*TT)   // 8192

#define BM 128
#define BN 128
#define BKE 64
#define GT 256

// ---------------- scratch ----------------
__device__ float g_qkv[(size_t)MROWS * 3 * CEMB];
__device__ float g_x2 [(size_t)MROWS * CEMB];
__device__ __half g_h [(size_t)MROWS * CEMB];       // ln out
__device__ __half g_y [(size_t)MROWS * CEMB];       // attn out
__device__ __half g_f [(size_t)MROWS * DFF];        // mlp hidden
// weights, transposed to [N,K] K-major, fp16
__device__ __half g_wa[(size_t)3*CEMB * CEMB];
__device__ __half g_wp[(size_t)CEMB * CEMB];
__device__ __half g_wf[(size_t)DFF * CEMB];
__device__ __half g_w2[(size_t)CEMB * DFF];
// attention operands
__device__ __half g_aq[(size_t)64 * TT * HS];
__device__ __half g_ak[(size_t)64 * TT * HS];
__device__ __half g_av[(size_t)64 * HS * TT];       // V transposed [bh][d][t]

// ---------------- PTX helpers ----------------
__device__ __forceinline__ uint32_t smem_u32(const void* p) {
    uint32_t a;
    asm("{ .reg .u64 t; cvta.to.shared.u64 t, %1; cvt.u32.u64 %0, t; }" : "=r"(a) : "l"(p));
    return a;
}
#define CP_ASYNC16(s, g) \
    asm volatile("cp.async.cg.shared.global [%0], [%1], 16;" :: "r"(s), "l"(g) : "memory")
#define CP_COMMIT() asm volatile("cp.async.commit_group;" ::: "memory")
#define CP_WAIT1()  asm volatile("cp.async.wait_group 1;" ::: "memory")
#define CP_WAIT0()  asm volatile("cp.async.wait_group 0;" ::: "memory")
#define LDSM_X4(r0, r1, r2, r3, addr) \
    asm volatile("ldmatrix.sync.aligned.m8n8.x4.shared.b16 {%0,%1,%2,%3}, [%4];" \
        : "=r"(r0), "=r"(r1), "=r"(r2), "=r"(r3) : "r"(addr))
#define MMAF16(c, a, b0v, b1v) \
    asm volatile("mma.sync.aligned.m16n8k16.row.col.f32.f16.f16.f32 " \
        "{%0,%1,%2,%3}, {%4,%5,%6,%7}, {%8,%9}, {%0,%1,%2,%3};" \
        : "+f"((c)[0]), "+f"((c)[1]), "+f"((c)[2]), "+f"((c)[3]) \
        : "r"((a)[0]), "r"((a)[1]), "r"((a)[2]), "r"((a)[3]), "r"(b0v), "r"(b1v))
#define STS32(addr, v) \
    asm volatile("st.shared.b32 [%0], %1;" :: "r"(addr), "r"(v) : "memory")

__device__ __forceinline__ uint32_t sw128(uint32_t off) { return off ^ ((off >> 3) & 0x70); }

__device__ __forceinline__ float gelu_f(float x) {
    float t = tanhf(0.79788456080286536f * (x + 0.044715f * x * x * x));
    return 0.5f * x * (1.0f + t);
}

union H4 { __half h[4]; uint2 u; };
union H2 { __half h[2]; uint32_t u; };

// ---------------- weight transpose + fp16 convert ----------------
__global__ __launch_bounds__(256) void wconv_kernel(const float* __restrict__ W,
    __half* __restrict__ Wf, int K, int N)
{
    __shared__ float t[32][33];
    int n0 = blockIdx.x * 32, k0 = blockIdx.y * 32;
    int tx = threadIdx.x & 31, ty = threadIdx.x >> 5;
    #pragma unroll
    for (int r = ty; r < 32; r += 8)
        t[r][tx] = W[(size_t)(k0 + r) * N + n0 + tx];
    __syncthreads();
    #pragma unroll
    for (int r = ty; r < 32; r += 8)
        Wf[(size_t)(n0 + r) * K + k0 + tx] = __float2half(t[tx][r]);
}

// ---------------- LayerNorm -> fp16 ----------------
__global__ __launch_bounds__(256) void ln_kernel(const float* __restrict__ x,
                                                 const float* __restrict__ g,
                                                 const float* __restrict__ b,
                                                 __half* __restrict__ oh)
{
    int row = blockIdx.x;
    int t = threadIdx.x;
    float4 v = ((const float4*)(x + (size_t)row * CEMB))[t];
    float s  = v.x + v.y + v.z + v.w;
    float ss = v.x*v.x + v.y*v.y + v.z*v.z + v.w*v.w;
    #pragma unroll
    for (int o = 16; o > 0; o >>= 1) {
        s  += __shfl_xor_sync(0xffffffffu, s,  o);
        ss += __shfl_xor_sync(0xffffffffu, ss, o);
    }
    __shared__ float red[16];
    int warp = t >> 5, lane = t & 31;
    if (lane == 0) { red[warp] = s; red[warp + 8] = ss; }
    __syncthreads();
    float sum = 0.f, sumsq = 0.f;
    #pragma unroll
    for (int w = 0; w < 8; w++) { sum += red[w]; sumsq += red[w + 8]; }
    float mu   = sum * (1.0f / CEMB);
    float var  = sumsq * (1.0f / CEMB) - mu * mu;
    float rstd = rsqrtf(var + 1e-5f);
    float4 gv = ((const float4*)g)[t];
    float4 bv = ((const float4*)b)[t];
    H4 o;
    o.h[0] = __float2half((v.x - mu) * rstd * gv.x + bv.x);
    o.h[1] = __float2half((v.y - mu) * rstd * gv.y + bv.y);
    o.h[2] = __float2half((v.z - mu) * rstd * gv.z + bv.z);
    o.h[3] = __float2half((v.w - mu) * rstd * gv.w + bv.w);
    *(uint2*)(oh + (size_t)row * CEMB + t * 4) = o.u;
}

// ---------------- HMMA fp16 GEMM: C = A @ B^T + bias ----------------
// stage: A 16K | B 16K = 32KB, double buffered -> 64KB, 2 CTAs/SM.
#define STAGE_BYTES 32768
#define SMEM_GEMM (2 * STAGE_BYTES + 1024)

template<int EPI>
__global__ __launch_bounds__(GT, 2) void gemm_f16(
    const __half* __restrict__ Ah,
    const __half* __restrict__ Bf,
    const float* __restrict__ bias, const float* __restrict__ R,
    float* __restrict__ Cf, __half* __restrict__ Ch,
    int M, int N, int K)
{
    extern __shared__ char dsm[];
    uintptr_t pa = ((uintptr_t)dsm + 1023) & ~(uintptr_t)1023;
    uint32_t sb = smem_u32((char*)pa);

    int tid = threadIdx.x;
    int wid = tid >> 5, lid = tid & 31;
    int wm = wid >> 1, wn = wid & 1;
    int m0 = blockIdx.y * BM, n0 = blockIdx.x * BN;

    const int NC = K / BKE;
    int lrow = tid >> 3;
    int lch  = tid & 7;

    auto load_stage = [&](int c) {
        int buf = c & 1;
        uint32_t st = sb + buf * STAGE_BYTES;
        int k0 = c * BKE;
        #pragma unroll
        for (int t = 0; t < 4; t++) {
            int row = lrow + t * 32;
            uint32_t so = sw128((uint32_t)(row * 128 + lch * 16));
            size_t ga = (size_t)(m0 + row) * K + k0 + lch * 8;
            CP_ASYNC16(st + so,         (const char*)(Ah + ga));
            size_t gb = (size_t)(n0 + row) * K + k0 + lch * 8;
            CP_ASYNC16(st + 16384 + so, (const char*)(Bf + gb));
        }
    };

    float acc[2][8][4];
    #pragma unroll
    for (int mi = 0; mi < 2; mi++)
        #pragma unroll
        for (int j = 0; j < 8; j++)
            #pragma unroll
            for (int q = 0; q < 4; q++) acc[mi][j][q] = 0.f;

    int lrow16 = lid & 15;
    int khalf  = lid >> 4;

    load_stage(0);
    CP_COMMIT();

    for (int c = 0; c < NC; c++) {
        if (c + 1 < NC) { load_stage(c + 1); CP_COMMIT(); CP_WAIT1(); }
        else            { CP_WAIT0(); }
        __syncthreads();

        uint32_t st = sb + (c & 1) * STAGE_BYTES;

        #pragma unroll
        for (int s = 0; s < 4; s++) {
            uint32_t aH[2][4], bH[4][4];
            #pragma unroll
            for (int mi = 0; mi < 2; mi++) {
                int row = wm * 32 + mi * 16 + lrow16;
                int ch = (s * 2 + khalf) ^ (row & 7);
                uint32_t ad = st + (uint32_t)(row * 128 + ch * 16);
                LDSM_X4(aH[mi][0], aH[mi][1], aH[mi][2], aH[mi][3], ad);
            }
            #pragma unroll
            for (int nb = 0; nb < 4; nb++) {
                int row = wn * 64 + nb * 16 + lrow16;
                int ch = (s * 2 + khalf) ^ (row & 7);
                uint32_t bd = st + 16384 + (uint32_t)(row * 128 + ch * 16);
                LDSM_X4(bH[nb][0], bH[nb][1], bH[nb][2], bH[nb][3], bd);
            }
            #pragma unroll
            for (int mi = 0; mi < 2; mi++) {
                #pragma unroll
                for (int nb = 0; nb < 4; nb++) {
                    MMAF16(acc[mi][nb*2],   aH[mi], bH[nb][0], bH[nb][2]);
                    MMAF16(acc[mi][nb*2+1], aH[mi], bH[nb][1], bH[nb][3]);
                }
            }
        }
        __syncthreads();
    }

    int gid = lid >> 2, tig = lid & 3;
    #pragma unroll
    for (int mi = 0; mi < 2; mi++) {
        #pragma unroll
        for (int j = 0; j < 8; j++) {
            int r0 = m0 + wm * 32 + mi * 16 + gid;
            int r1 = r0 + 8;
            int col = n0 + wn * 64 + j * 8 + tig * 2;
            float b0 = bias[col], b1 = bias[col + 1];
            float v0 = acc[mi][j][0] + b0, v1 = acc[mi][j][1] + b1;
            float v2 = acc[mi][j][2] + b0, v3 = acc[mi][j][3] + b1;
            if (EPI == 1) {
                float2 q0 = *(const float2*)(R + (size_t)r0 * N + col);
                float2 q1 = *(const float2*)(R + (size_t)r1 * N + col);
                v0 += q0.x; v1 += q0.y; v2 += q1.x; v3 += q1.y;
            }
            if (EPI == 2) {
                v0 = gelu_f(v0); v1 = gelu_f(v1); v2 = gelu_f(v2); v3 = gelu_f(v3);
                H2 h0, h1;
                h0.h[0] = __float2half(v0); h0.h[1] = __float2half(v1);
                h1.h[0] = __float2half(v2); h1.h[1] = __float2half(v3);
                *(uint32_t*)(Ch + (size_t)r0 * N + col) = h0.u;
                *(uint32_t*)(Ch + (size_t)r1 * N + col) = h1.u;
            } else {
                *(float2*)(Cf + (size_t)r0 * N + col) = make_float2(v0, v1);
                *(float2*)(Cf + (size_t)r1 * N + col) = make_float2(v2, v3);
            }
        }
    }
}

// ---------------- attention prep ----------------
__global__ __launch_bounds__(256) void attnprep_kernel(
    const float* __restrict__ qkv,
    __half* __restrict__ Qf, __half* __restrict__ Kf, __half* __restrict__ Vt)
{
    __shared__ float vs[64][65];
    int tb = blockIdx.x, bh = blockIdx.y;
    int b = bh >> 4, hd = bh & 15;
    int t0 = tb * 64;
    int tid = threadIdx.x;

    for (int i = tid; i < 1024; i += 256) {
        int r = i >> 4, c4 = (i & 15) * 4;
        const float* base = qkv + ((size_t)(b * TT + t0 + r)) * (3 * CEMB) + hd * HS + c4;
        float4 q = *(const float4*)base;
        float4 k = *(const float4*)(base + CEMB);
        float4 v = *(const float4*)(base + 2 * CEMB);
        H4 qq, kk;
        qq.h[0] = __float2half(q.x * 0.125f); qq.h[1] = __float2half(q.y * 0.125f);
        qq.h[2] = __float2half(q.z * 0.125f); qq.h[3] = __float2half(q.w * 0.125f);
        kk.h[0] = __float2half(k.x); kk.h[1] = __float2half(k.y);
        kk.h[2] = __float2half(k.z); kk.h[3] = __float2half(k.w);
        size_t qo = ((size_t)bh * TT + t0 + r) * HS + c4;
        *(uint2*)(Qf + qo) = qq.u;
        *(uint2*)(Kf + qo) = kk.u;
        vs[r][c4] = v.x; vs[r][c4+1] = v.y; vs[r][c4+2] = v.z; vs[r][c4+3] = v.w;
    }
    __syncthreads();
    for (int i = tid; i < 1024; i += 256) {
        int d = i >> 4, tq = (i & 15) * 4;
        H4 vv;
        vv.h[0] = __float2half(vs[tq+0][d]);
        vv.h[1] = __float2half(vs[tq+1][d]);
        vv.h[2] = __float2half(vs[tq+2][d]);
        vv.h[3] = __float2half(vs[tq+3][d]);
        size_t vo = ((size_t)bh * HS + d) * TT + t0 + tq;
        *(uint2*)(Vt + vo) = vv.u;
    }
}

// ---------------- HMMA flash attention (all fp16) ----------------
// smem: Q 16K @0 | buf(b) @16K+16K*b: K 8K, Vt 8K | P 16K @48K = 64KB
#define ATSM_BUF(b) (16384 + (b) * 16384)
#define ATSM_P 49152
#define ATT_SMEM (65536 + 1024)

__global__ __launch_bounds__(256, 2) void attn_mma_kernel(
    const __half* __restrict__ Qf_, const __half* __restrict__ Kf_,
    const __half* __restrict__ Vt_,
    __half* __restrict__ yo)
{
    extern __shared__ char dsm[];
    uintptr_t pa = ((uintptr_t)dsm + 1023) & ~(uintptr_t)1023;
    uint32_t sb = smem_u32((char*)pa);

    int qt = gridDim.x - 1 - blockIdx.x;
    int q0 = qt * 128;
    int bh = blockIdx.y;
    int b = bh >> 4, hd = bh & 15;
    size_t hq = (size_t)bh * TT * HS;

    int tid = threadIdx.x;
    int wid = tid >> 5, lid = tid & 31;
    int lrow16 = lid & 15, khalf = lid >> 4;
    int arow = wid * 16 + lrow16;

    auto load_kv = [&](int jb, int buf) {
        int j0 = jb * 64;
        uint32_t st = sb + ATSM_BUF(buf);
        const char* kf = (const char*)(Kf_ + hq + (size_t)j0 * HS);
        const char* vt = (const char*)(Vt_ + hq) + (size_t)j0 * 2;
        #pragma unroll
        for (int i = tid; i < 512; i += 256) {
            int row = i >> 3, ch = i & 7;
            uint32_t so = sw128((uint32_t)(row * 128 + ch * 16));
            CP_ASYNC16(st + so,        kf + row * 128 + ch * 16);
            CP_ASYNC16(st + 8192 + so, vt + (size_t)row * (TT * 2) + ch * 16);
        }
    };

    {
        const char* qf = (const char*)(Qf_ + hq + (size_t)q0 * HS);
        #pragma unroll
        for (int i = tid; i < 1024; i += 256) {
            int row = i >> 3, ch = i & 7;
            uint32_t so = sw128((uint32_t)(row * 128 + ch * 16));
            CP_ASYNC16(sb + so, qf + row * 128 + ch * 16);
        }
    }
    load_kv(0, 0);
    CP_COMMIT();

    float m_[2] = {-INFINITY, -INFINITY};
    float l_[2] = {0.f, 0.f};
    float acc[8][4];
    #pragma unroll
    for (int nb = 0; nb < 8; nb++)
        #pragma unroll
        for (int q = 0; q < 4; q++) acc[nb][q] = 0.f;

    int jbmax = q0 / 64 + 1;
    for (int jb = 0; jb <= jbmax; jb++) {
        int buf = jb & 1;
        CP_WAIT0();
        __syncthreads();
        if (jb < jbmax) { load_kv(jb + 1, buf ^ 1); CP_COMMIT(); }

        uint32_t sK = sb + ATSM_BUF(buf);
        uint32_t sV = sK + 8192;

        float s[8][4];
        #pragma unroll
        for (int nb = 0; nb < 8; nb++)
            #pragma unroll
            for (int q = 0; q < 4; q++) s[nb][q] = 0.f;

        #pragma unroll
        for (int ks = 0; ks < 4; ks++) {
            int ach = (ks * 2 + khalf) ^ (arow & 7);
            uint32_t aa = sb + (uint32_t)(arow * 128 + ach * 16);
            uint32_t aH[4];
            LDSM_X4(aH[0], aH[1], aH[2], aH[3], aa);
            uint32_t bH[4][4];
            #pragma unroll
            for (int nb2 = 0; nb2 < 4; nb2++) {
                int br = nb2 * 16 + lrow16;
                int bch = (ks * 2 + khalf) ^ (br & 7);
                uint32_t ba = sK + (uint32_t)(br * 128 + bch * 16);
                LDSM_X4(bH[nb2][0], bH[nb2][1], bH[nb2][2], bH[nb2][3], ba);
            }
            #pragma unroll
            for (int nb2 = 0; nb2 < 4; nb2++) {
                MMAF16(s[nb2*2],   aH, bH[nb2][0], bH[nb2][2]);
                MMAF16(s[nb2*2+1], aH, bH[nb2][1], bH[nb2][3]);
            }
        }

        int j0 = jb * 64;
        if (j0 + 63 > q0 + wid * 16) {
            int r0g = q0 + wid * 16 + (lid >> 2);
            #pragma unroll
            for (int nb = 0; nb < 8; nb++) {
                int c0 = j0 + nb * 8 + (lid & 3) * 2;
                if (c0     > r0g)     s[nb][0] = -INFINITY;
                if (c0 + 1 > r0g)     s[nb][1] = -INFINITY;
                if (c0     > r0g + 8) s[nb][2] = -INFINITY;
                if (c0 + 1 > r0g + 8) s[nb][3] = -INFINITY;
            }
        }

        float rmax[2] = {-INFINITY, -INFINITY};
        #pragma unroll
        for (int nb = 0; nb < 8; nb++) {
            rmax[0] = fmaxf(rmax[0], fmaxf(s[nb][0], s[nb][1]));
            rmax[1] = fmaxf(rmax[1], fmaxf(s[nb][2], s[nb][3]));
        }
        #pragma unroll
        for (int o = 1; o <= 2; o <<= 1) {
            rmax[0] = fmaxf(rmax[0], __shfl_xor_sync(0xffffffffu, rmax[0], o));
            rmax[1] = fmaxf(rmax[1], __shfl_xor_sync(0xffffffffu, rmax[1], o));
        }
        float mn0 = fmaxf(m_[0], rmax[0]);
        float mn1 = fmaxf(m_[1], rmax[1]);
        float alpha0 = __expf(m_[0] - mn0);
        float alpha1 = __expf(m_[1] - mn1);
        m_[0] = mn0; m_[1] = mn1;
        float rs[2] = {0.f, 0.f};
        #pragma unroll
        for (int nb = 0; nb < 8; nb++) {
            s[nb][0] = __expf(s[nb][0] - mn0); rs[0] += s[nb][0];
            s[nb][1] = __expf(s[nb][1] - mn0); rs[0] += s[nb][1];
            s[nb][2] = __expf(s[nb][2] - mn1); rs[1] += s[nb][2];
            s[nb][3] = __expf(s[nb][3] - mn1); rs[1] += s[nb][3];
        }
        #pragma unroll
        for (int o = 1; o <= 2; o <<= 1) {
            rs[0] += __shfl_xor_sync(0xffffffffu, rs[0], o);
            rs[1] += __shfl_xor_sync(0xffffffffu, rs[1], o);
        }
        l_[0] = l_[0] * alpha0 + rs[0];
        l_[1] = l_[1] * alpha1 + rs[1];
        #pragma unroll
        for (int nb = 0; nb < 8; nb++) {
            acc[nb][0] *= alpha0; acc[nb][1] *= alpha0;
            acc[nb][2] *= alpha1; acc[nb][3] *= alpha1;
        }

        {
            int r0 = wid * 16 + (lid >> 2);
            #pragma unroll
            for (int nb = 0; nb < 8; nb++) {
                int coff = (nb * 8 + (lid & 3) * 2) * 2;
                uint32_t o0 = sw128((uint32_t)(r0 * 128 + coff));
                uint32_t o1 = sw128((uint32_t)((r0 + 8) * 128 + coff));
                H2 h;
                h.h[0] = __float2half(s[nb][0]); h.h[1] = __float2half(s[nb][1]);
                STS32(sb + ATSM_P + o0, h.u);
                h.h[0] = __float2half(s[nb][2]); h.h[1] = __float2half(s[nb][3]);
                STS32(sb + ATSM_P + o1, h.u);
            }
        }
        __syncwarp();

        #pragma unroll
        for (int ks = 0; ks < 4; ks++) {
            int ach = (ks * 2 + khalf) ^ (arow & 7);
            uint32_t paddr = sb + ATSM_P + (uint32_t)(arow * 128 + ach * 16);
            uint32_t pH[4];
            LDSM_X4(pH[0], pH[1], pH[2], pH[3], paddr);
            uint32_t bH[4][4];
            #pragma unroll
            for (int nb2 = 0; nb2 < 4; nb2++) {
                int br = nb2 * 16 + lrow16;
                int bch = (ks * 2 + khalf) ^ (br & 7);
                uint32_t ba = sV + (uint32_t)(br * 128 + bch * 16);
                LDSM_X4(bH[nb2][0], bH[nb2][1], bH[nb2][2], bH[nb2][3], ba);
            }
            #pragma unroll
            for (int nb2 = 0; nb2 < 4; nb2++) {
                MMAF16(acc[nb2*2],   pH, bH[nb2][0], bH[nb2][2]);
                MMAF16(acc[nb2*2+1], pH, bH[nb2][1], bH[nb2][3]);
            }
        }
    }

    float inv0 = 1.0f / l_[0];
    float inv1 = 1.0f / l_[1];
    size_t r0g = (size_t)b * TT + q0 + wid * 16 + (lid >> 2);
    #pragma unroll
    for (int nb = 0; nb < 8; nb++) {
        int col = hd * HS + nb * 8 + (lid & 3) * 2;
        H2 h;
        h.h[0] = __float2half(acc[nb][0] * inv0);
        h.h[1] = __float2half(acc[nb][1] * inv0);
        *(uint32_t*)(yo + r0g * CEMB + col) = h.u;
        h.h[0] = __float2half(acc[nb][2] * inv1);
        h.h[1] = __float2half(acc[nb][3] * inv1);
        *(uint32_t*)(yo + (r0g + 8) * CEMB + col) = h.u;
    }
}

// ---------------- launch ----------------
extern "C" void kernel_launch(void* const* d_in, const int* in_sizes, int n_in,
                              void* d_out, int out_size)
{
    const float* x      = (const float*)d_in[0];
    const float* ln1_g  = (const float*)d_in[1];
    const float* ln1_b  = (const float*)d_in[2];
    const float* w_attn = (const float*)d_in[3];
    const float* b_attn = (const float*)d_in[4];
    const float* w_proj = (const float*)d_in[5];
    const float* b_proj = (const float*)d_in[6];
    const float* ln2_g  = (const float*)d_in[7];
    const float* ln2_b  = (const float*)d_in[8];
    const float* w_fc   = (const float*)d_in[9];
    const float* b_fc   = (const float*)d_in[10];
    const float* w_fc2  = (const float*)d_in[11];
    const float* b_fc2  = (const float*)d_in[12];
    float* out = (float*)d_out;

    float *qkv, *x2;
    __half *h, *y, *f;
    __half *wa, *wp, *wf, *w2;
    __half *aq, *ak, *av;
    cudaGetSymbolAddress((void**)&qkv, g_qkv);
    cudaGetSymbolAddress((void**)&x2,  g_x2);
    cudaGetSymbolAddress((void**)&h,   g_h);
    cudaGetSymbolAddress((void**)&y,   g_y);
    cudaGetSymbolAddress((void**)&f,   g_f);
    cudaGetSymbolAddress((void**)&wa,  g_wa);
    cudaGetSymbolAddress((void**)&wp,  g_wp);
    cudaGetSymbolAddress((void**)&wf,  g_wf);
    cudaGetSymbolAddress((void**)&w2,  g_w2);
    cudaGetSymbolAddress((void**)&aq,  g_aq);
    cudaGetSymbolAddress((void**)&ak,  g_ak);
    cudaGetSymbolAddress((void**)&av,  g_av);

    cudaFuncSetAttribute(gemm_f16<0>, cudaFuncAttributeMaxDynamicSharedMemorySize, SMEM_GEMM);
    cudaFuncSetAttribute(gemm_f16<1>, cudaFuncAttributeMaxDynamicSharedMemorySize, SMEM_GEMM);
    cudaFuncSetAttribute(gemm_f16<2>, cudaFuncAttributeMaxDynamicSharedMemorySize, SMEM_GEMM);
    cudaFuncSetAttribute(attn_mma_kernel, cudaFuncAttributeMaxDynamicSharedMemorySize, ATT_SMEM);

    dim3 blk(256);

    wconv_kernel<<<dim3(3*CEMB/32, CEMB/32), blk>>>(w_attn, wa, CEMB, 3*CEMB);
    wconv_kernel<<<dim3(CEMB/32,   CEMB/32), blk>>>(w_proj, wp, CEMB, CEMB);
    wconv_kernel<<<dim3(DFF/32,    CEMB/32), blk>>>(w_fc,   wf, CEMB, DFF);
    wconv_kernel<<<dim3(CEMB/32,   DFF/32),  blk>>>(w_fc2,  w2, DFF,  CEMB);

    ln_kernel<<<MROWS, blk>>>(x, ln1_g, ln1_b, h);
    gemm_f16<0><<<dim3(3*CEMB/BN, MROWS/BM), GT, SMEM_GEMM>>>(
        h, wa, b_attn, nullptr, qkv, nullptr, MROWS, 3*CEMB, CEMB);
    attnprep_kernel<<<dim3(TT/64, BB*NHEADS), blk>>>(qkv, aq, ak, av);
    attn_mma_kernel<<<dim3(TT/128, BB*NHEADS), blk, ATT_SMEM>>>(aq, ak, av, y);
    gemm_f16<1><<<dim3(CEMB/BN, MROWS/BM), GT, SMEM_GEMM>>>(
        y, wp, b_proj, x, x2, nullptr, MROWS, CEMB, CEMB);
    ln_kernel<<<MROWS, blk>>>(x2, ln2_g, ln2_b, h);
    gemm_f16<2><<<dim3(DFF/BN, MROWS/BM), GT, SMEM_GEMM>>>(
        h, wf, b_fc, nullptr, nullptr, f, MROWS, DFF, CEMB);
    gemm_f16<1><<<dim3(CEMB/BN, MROWS/BM), GT, SMEM_GEMM>>>(
        f, w2, b_fc2, x2, out, nullptr, MROWS, CEMB, DFF);
}